// round 10
// baseline (speedup 1.0000x reference)
#include <cuda_runtime.h>
#include <cuda_bf16.h>
#include <math.h>
#include <stdint.h>

#define NB 32
#define NC 64
#define NL 2048
#define S0 341
#define S1 341
#define S2 343
#define SKP 352      // padded K stride
#define DPAD 384     // padded d dimension for A splits
#define TSP 68       // gram transposed-smem row stride (64 + 4)
#define NROWS 2048   // NB * NC

// Scratch (device globals; allocation-free per harness rules)
__device__ __nv_bfloat16 g_bbf[3][3][NROWS][SKP];   // [split][band][row][s]
__device__ __nv_bfloat16 g_abf[3][3][DPAD][SKP];    // [split][band][d][s]
__device__ float g_Y[3][NROWS][SKP];
__device__ float g_dist[3][NB][NC][NC];

// ---------------------------------------------------------------------------
// f32x2 helpers (packed fp32 FFMA2) — used by gram kernel
// ---------------------------------------------------------------------------
__device__ __forceinline__ unsigned long long pk2(float lo, float hi) {
    unsigned long long r;
    asm("mov.b64 %0, {%1, %2};" : "=l"(r) : "f"(lo), "f"(hi));
    return r;
}
__device__ __forceinline__ void fma2(unsigned long long& d,
                                     unsigned long long a, unsigned long long b) {
    asm("fma.rn.f32x2 %0, %1, %2, %0;" : "+l"(d) : "l"(a), "l"(b));
}
__device__ __forceinline__ void add2(unsigned long long& d, unsigned long long a) {
    asm("add.rn.f32x2 %0, %0, %1;" : "+l"(d) : "l"(a));
}
__device__ __forceinline__ float2 upk2(unsigned long long v) {
    float lo, hi;
    asm("mov.b64 {%0, %1}, %2;" : "=f"(lo), "=f"(hi) : "l"(v));
    return make_float2(lo, hi);
}

// bf16x3 split: x ~= b0 + b1 + b2 with error ~2^-26 * |x|
__device__ __forceinline__ void bsplit(float x, __nv_bfloat16& b0,
                                       __nv_bfloat16& b1, __nv_bfloat16& b2) {
    b0 = __float2bfloat16(x);
    float r = x - __bfloat162float(b0);
    b1 = __float2bfloat16(r);
    r -= __bfloat162float(b1);
    b2 = __float2bfloat16(r);
}

// m16n8k16 bf16 MMA, fp32 accumulate (legacy HMMA path, sm_80+ base target)
__device__ __forceinline__ void mma16816(float* d, const uint32_t* a,
                                         uint32_t b0, uint32_t b1) {
    asm volatile(
        "mma.sync.aligned.m16n8k16.row.col.f32.bf16.bf16.f32 "
        "{%0,%1,%2,%3},{%4,%5,%6,%7},{%8,%9},{%0,%1,%2,%3};"
        : "+f"(d[0]), "+f"(d[1]), "+f"(d[2]), "+f"(d[3])
        : "r"(a[0]), "r"(a[1]), "r"(a[2]), "r"(a[3]), "r"(b0), "r"(b1));
}

// ---------------------------------------------------------------------------
// Kernel 0: split A matrices into zero-padded bf16x3 arrays
// grid (DPAD, 3), 128 threads
// ---------------------------------------------------------------------------
__global__ __launch_bounds__(128) void aprep_kernel(const float* __restrict__ A0,
                                                    const float* __restrict__ A1,
                                                    const float* __restrict__ A2) {
    const int d = blockIdx.x;
    const int k = blockIdx.y;
    const int sk = (k == 2) ? S2 : S0;
    const float* A = (k == 0) ? A0 : ((k == 1) ? A1 : A2);
    for (int s = threadIdx.x; s < SKP; s += 128) {
        const float v = (d < sk && s < sk) ? A[(size_t)d * sk + s] : 0.0f;
        __nv_bfloat16 b0, b1, b2;
        bsplit(v, b0, b1, b2);
        g_abf[0][k][d][s] = b0;
        g_abf[1][k][d][s] = b1;
        g_abf[2][k][d][s] = b2;
    }
}

// ---------------------------------------------------------------------------
// Kernel 1: rfft magnitude via real-packed 1024-pt radix-4 FFT
// epilogue now emits bf16x3 splits of the band magnitudes
// ---------------------------------------------------------------------------
__device__ __forceinline__ unsigned drev10(unsigned n) {
    unsigned r = __brev(n) >> 22;
    return ((r & 0x155u) << 1) | ((r >> 1) & 0x155u);
}

__global__ __launch_bounds__(256) void fft_kernel(const float* __restrict__ X) {
    __shared__ float sre[1024], sim[1024], wre[1025], wim[1025];
    const int row = blockIdx.x;
    const int t = threadIdx.x;
    const float2* x2 = (const float2*)(X + (size_t)row * NL);

    #pragma unroll
    for (int m = 0; m < 4; m++) {
        const int i = t + m * 256;
        float sn, cs;
        sincospif((float)i * (1.0f / 512.0f), &sn, &cs);
        wre[i] = cs;
        wim[i] = -sn;
        const float2 v = x2[i];
        const unsigned dr = drev10((unsigned)i);
        sre[dr] = v.x;
        sim[dr] = v.y;
    }
    if (t == 0) { wre[1024] = -1.0f; wim[1024] = 0.0f; }
    __syncthreads();

    {
        float4 xr = *(float4*)&sre[4 * t];
        float4 xi = *(float4*)&sim[4 * t];
        const float s02r = xr.x + xr.z, s02i = xi.x + xi.z;
        const float d02r = xr.x - xr.z, d02i = xi.x - xi.z;
        const float s13r = xr.y + xr.w, s13i = xi.y + xi.w;
        const float d13r = xr.y - xr.w, d13i = xi.y - xi.w;
        float4 yr, yi;
        yr.x = s02r + s13r;  yi.x = s02i + s13i;
        yr.y = d02r + d13i;  yi.y = d02i - d13r;
        yr.z = s02r - s13r;  yi.z = s02i - s13i;
        yr.w = d02r - d13i;  yi.w = d02i + d13r;
        *(float4*)&sre[4 * t] = yr;
        *(float4*)&sim[4 * t] = yi;
    }
    __syncthreads();

    #pragma unroll
    for (int s = 2; s <= 5; s++) {
        const int mm = 1 << (2 * (s - 1));
        const int j = t & (mm - 1);
        const int base = ((t >> (2 * (s - 1))) << (2 * s)) + j;
        const int r1 = j << (10 - 2 * s);

        const float x0r = sre[base],          x0i = sim[base];
        const float x1r = sre[base + mm],     x1i = sim[base + mm];
        const float x2r = sre[base + 2 * mm], x2i = sim[base + 2 * mm];
        const float x3r = sre[base + 3 * mm], x3i = sim[base + 3 * mm];
        const float w1r = wre[r1],     w1i = wim[r1];
        const float w2r = wre[2 * r1], w2i = wim[2 * r1];
        const float w3r = wre[3 * r1], w3i = wim[3 * r1];

        const float u1r = x1r * w1r - x1i * w1i, u1i = x1r * w1i + x1i * w1r;
        const float u2r = x2r * w2r - x2i * w2i, u2i = x2r * w2i + x2i * w2r;
        const float u3r = x3r * w3r - x3i * w3i, u3i = x3r * w3i + x3i * w3r;

        const float s02r = x0r + u2r, s02i = x0i + u2i;
        const float d02r = x0r - u2r, d02i = x0i - u2i;
        const float s13r = u1r + u3r, s13i = u1i + u3i;
        const float d13r = u1r - u3r, d13i = u1i - u3i;

        sre[base]          = s02r + s13r;  sim[base]          = s02i + s13i;
        sre[base + mm]     = d02r + d13i;  sim[base + mm]     = d02i - d13r;
        sre[base + 2 * mm] = s02r - s13r;  sim[base + 2 * mm] = s02i - s13i;
        sre[base + 3 * mm] = d02r - d13i;  sim[base + 3 * mm] = d02i + d13r;
        __syncthreads();
    }

    const float CR = 0.999995293809576f;
    const float CI = -0.003067956762966f;
    for (int pos = t; pos < 3 * SKP; pos += 256) {
        int band, off, k, sk;
        if (pos < SKP)            { band = 0; off = pos;           k = off;       sk = S0; }
        else if (pos < 2 * SKP)   { band = 1; off = pos - SKP;     k = S0 + off;  sk = S1; }
        else                      { band = 2; off = pos - 2 * SKP; k = 682 + off; sk = S2; }
        float mag = 0.0f;
        if (off < sk) {
            const int ka = k & 1023;
            const int kb = (1024 - k) & 1023;
            const float z1r = sre[ka], z1i = sim[ka];
            const float z2r = sre[kb], z2i = sim[kb];
            const float zer = z1r + z2r, zei = z1i - z2i;
            const float zor = z1i + z2i, zoi = z2r - z1r;
            const int m = k >> 1;
            float cs = wre[m], msn = wim[m];
            if (k & 1) {
                const float c2 = cs * CR - msn * CI;
                msn = cs * CI + msn * CR;
                cs = c2;
            }
            const float xr = zer + cs * zor - msn * zoi;
            const float xi = zei + cs * zoi + msn * zor;
            mag = 0.5f * sqrtf(xr * xr + xi * xi);
        }
        __nv_bfloat16 b0, b1, b2;
        bsplit(mag, b0, b1, b2);
        g_bbf[0][band][row][off] = b0;
        g_bbf[1][band][row][off] = b1;
        g_bbf[2][band][row][off] = b2;
    }
}

// ---------------------------------------------------------------------------
// Kernel 2: bf16x3 split GEMM on HMMA (mma.sync m16n8k16).
// Y[k][r][d] = sum_s band[r][s] * A[d][s], fp32-accurate via 6 split products.
// Block: 128(M) x 96(N), 8 warps (warp tile 32x48), K chunks of 32.
// smem rows stride 40 bf16 (80B) -> conflict-free fragment LDS.
// grid (4, 16, 3)
// ---------------------------------------------------------------------------
#define BSTRIDE 40
#define SM_BAND_SPLIT (128 * BSTRIDE)          // 5120 bf16 per split
#define SM_A_BASE     (3 * SM_BAND_SPLIT)      // 15360
#define SM_A_SPLIT    (96 * BSTRIDE)           // 3840
#define GEMM_SMEM_BF  (SM_A_BASE + 3 * SM_A_SPLIT)   // 26880 bf16 = 53760 B

__global__ __launch_bounds__(256) void gemm_mma_kernel() {
    extern __shared__ __align__(16) __nv_bfloat16 sm[];

    const int k = blockIdx.z;
    const int n0 = blockIdx.x * 96;
    const int r0 = blockIdx.y * 128;
    const int t = threadIdx.x;
    const int wid = t >> 5;
    const int lane = t & 31;
    const int g = lane >> 2;
    const int tq = lane & 3;
    const int wm = (wid & 3) * 32;     // warp M offset (4 warps)
    const int wn = (wid >> 2) * 48;    // warp N offset (2 warps)

    float acc[2][6][4];
    #pragma unroll
    for (int mf = 0; mf < 2; mf++)
        #pragma unroll
        for (int nf = 0; nf < 6; nf++)
            #pragma unroll
            for (int c = 0; c < 4; c++) acc[mf][nf][c] = 0.0f;

    const int ci[6] = {0, 0, 1, 0, 1, 2};
    const int cj[6] = {0, 1, 0, 2, 1, 0};

    for (int ck = 0; ck < 11; ck++) {
        const int s0 = ck * 32;
        // stage band tile: 3 splits x 128 rows x 32 k  (1536 uint4)
        for (int i = t; i < 1536; i += 256) {
            const int sp = i >> 9;
            const int rem = i & 511;
            const int rr = rem >> 2;
            const int seg = rem & 3;
            const uint4 v = *(const uint4*)&g_bbf[sp][k][r0 + rr][s0 + seg * 8];
            *(uint4*)&sm[sp * SM_BAND_SPLIT + rr * BSTRIDE + seg * 8] = v;
        }
        // stage A tile: 3 splits x 96 rows x 32 k  (1152 uint4)
        for (int i = t; i < 1152; i += 256) {
            const int sp = i / 384;
            const int rem = i % 384;
            const int rr = rem >> 2;
            const int seg = rem & 3;
            const uint4 v = *(const uint4*)&g_abf[sp][k][n0 + rr][s0 + seg * 8];
            *(uint4*)&sm[SM_A_BASE + sp * SM_A_SPLIT + rr * BSTRIDE + seg * 8] = v;
        }
        __syncthreads();

        #pragma unroll
        for (int m = 0; m < 6; m++) {
            const __nv_bfloat16* pb = sm + ci[m] * SM_BAND_SPLIT;
            const __nv_bfloat16* pa = sm + SM_A_BASE + cj[m] * SM_A_SPLIT;
            #pragma unroll
            for (int ks = 0; ks < 2; ks++) {
                const int kk = ks * 16 + 2 * tq;
                uint32_t a[2][4];
                #pragma unroll
                for (int mf = 0; mf < 2; mf++) {
                    const int rb = wm + mf * 16;
                    a[mf][0] = *(const uint32_t*)(pb + (rb + g) * BSTRIDE + kk);
                    a[mf][1] = *(const uint32_t*)(pb + (rb + g + 8) * BSTRIDE + kk);
                    a[mf][2] = *(const uint32_t*)(pb + (rb + g) * BSTRIDE + kk + 8);
                    a[mf][3] = *(const uint32_t*)(pb + (rb + g + 8) * BSTRIDE + kk + 8);
                }
                #pragma unroll
                for (int nf = 0; nf < 6; nf++) {
                    const int nb = wn + nf * 8;
                    const uint32_t b0 = *(const uint32_t*)(pa + (nb + g) * BSTRIDE + kk);
                    const uint32_t b1 = *(const uint32_t*)(pa + (nb + g) * BSTRIDE + kk + 8);
                    mma16816(acc[0][nf], a[0], b0, b1);
                    mma16816(acc[1][nf], a[1], b0, b1);
                }
            }
        }
        __syncthreads();
    }

    // epilogue: fragments -> g_Y fp32 (guard d < SKP; N padded to 384)
    #pragma unroll
    for (int mf = 0; mf < 2; mf++) {
        const int row = r0 + wm + mf * 16 + g;
        #pragma unroll
        for (int nf = 0; nf < 6; nf++) {
            const int dd = n0 + wn + nf * 8;
            if (dd < SKP) {
                *(float2*)&g_Y[k][row][dd + 2 * tq] =
                    make_float2(acc[mf][nf][0], acc[mf][nf][1]);
                *(float2*)&g_Y[k][row + 8][dd + 2 * tq] =
                    make_float2(acc[mf][nf][2], acc[mf][nf][3]);
            }
        }
    }
}

// ---------------------------------------------------------------------------
// Kernel 3: gram/dist (unchanged from R8 — known-good)
// ---------------------------------------------------------------------------
__global__ __launch_bounds__(1024) void gram_dist_kernel() {
    extern __shared__ float smemf[];
    float* sYT = smemf;
    unsigned long long* part = (unsigned long long*)(smemf + SKP * TSP);
    __shared__ float q[64];

    const int b = blockIdx.x;
    const int k = blockIdx.y;
    const int t = threadIdx.x;

    {
        const int r_ = t & 7;
        const int c4 = t >> 3;
        if (c4 < SKP / 4) {
            const float* src = &g_Y[k][b * 64][0];
            #pragma unroll
            for (int rb = 0; rb < 64; rb += 8) {
                const int r = rb + r_;
                const float4 v = *(const float4*)&src[(size_t)r * SKP + c4 * 4];
                const int d = c4 * 4;
                sYT[(d + 0) * TSP + r] = v.x;
                sYT[(d + 1) * TSP + r] = v.y;
                sYT[(d + 2) * TSP + r] = v.z;
                sYT[(d + 3) * TSP + r] = v.w;
            }
        }
    }
    __syncthreads();

    const int half = t >> 8;
    const int tt = t & 255;
    const int ty = tt >> 4;
    const int tx = tt & 15;
    const int ti = ty * 4;
    const int tj = tx * 4;

    unsigned long long acc[2][4];
    #pragma unroll
    for (int p = 0; p < 2; p++)
        #pragma unroll
        for (int j = 0; j < 4; j++) acc[p][j] = 0ull;

    const float* base = &sYT[half * 88 * TSP];
    #pragma unroll 4
    for (int dd = 0; dd < 88; dd++) {
        const float* rowp = base + dd * TSP;
        const ulonglong2 a = *(const ulonglong2*)&rowp[ti];
        const float4 bb = *(const float4*)&rowp[tj];
        const unsigned long long bd0 = pk2(bb.x, bb.x);
        const unsigned long long bd1 = pk2(bb.y, bb.y);
        const unsigned long long bd2 = pk2(bb.z, bb.z);
        const unsigned long long bd3 = pk2(bb.w, bb.w);
        fma2(acc[0][0], a.x, bd0);  fma2(acc[0][1], a.x, bd1);
        fma2(acc[0][2], a.x, bd2);  fma2(acc[0][3], a.x, bd3);
        fma2(acc[1][0], a.y, bd0);  fma2(acc[1][1], a.y, bd1);
        fma2(acc[1][2], a.y, bd2);  fma2(acc[1][3], a.y, bd3);
    }

    if (half != 0) {
        unsigned long long* dst = &part[((half - 1) * 256 + tt) * 8];
        #pragma unroll
        for (int p = 0; p < 2; p++)
            #pragma unroll
            for (int j = 0; j < 4; j++) dst[p * 4 + j] = acc[p][j];
    }
    __syncthreads();

    if (half == 0) {
        #pragma unroll
        for (int h = 0; h < 3; h++) {
            const unsigned long long* src = &part[(h * 256 + tt) * 8];
            #pragma unroll
            for (int p = 0; p < 2; p++)
                #pragma unroll
                for (int j = 0; j < 4; j++) add2(acc[p][j], src[p * 4 + j]);
        }
        if (ty == tx) {
            q[ti + 0] = upk2(acc[0][0]).x;
            q[ti + 1] = upk2(acc[0][1]).y;
            q[ti + 2] = upk2(acc[1][2]).x;
            q[ti + 3] = upk2(acc[1][3]).y;
        }
    }
    __syncthreads();

    if (half == 0) {
        #pragma unroll
        for (int p = 0; p < 2; p++) {
            const float2 g0 = upk2(acc[p][0]);
            const float2 g1 = upk2(acc[p][1]);
            const float2 g2 = upk2(acc[p][2]);
            const float2 g3 = upk2(acc[p][3]);
            const float qj0 = q[tj + 0], qj1 = q[tj + 1];
            const float qj2 = q[tj + 2], qj3 = q[tj + 3];
            const int r = ti + 2 * p;
            const float qlo = q[r], qhi = q[r + 1];
            float4 lo, hi;
            lo.x = fmaxf(qlo + qj0 - 2.0f * g0.x, 0.0f);
            lo.y = fmaxf(qlo + qj1 - 2.0f * g1.x, 0.0f);
            lo.z = fmaxf(qlo + qj2 - 2.0f * g2.x, 0.0f);
            lo.w = fmaxf(qlo + qj3 - 2.0f * g3.x, 0.0f);
            hi.x = fmaxf(qhi + qj0 - 2.0f * g0.y, 0.0f);
            hi.y = fmaxf(qhi + qj1 - 2.0f * g1.y, 0.0f);
            hi.z = fmaxf(qhi + qj2 - 2.0f * g2.y, 0.0f);
            hi.w = fmaxf(qhi + qj3 - 2.0f * g3.y, 0.0f);
            *(float4*)&g_dist[k][b][r][tj]     = lo;
            *(float4*)&g_dist[k][b][r + 1][tj] = hi;
        }
    }
}

// ---------------------------------------------------------------------------
// Kernel 4: mask (unchanged)
// ---------------------------------------------------------------------------
__global__ __launch_bounds__(256) void mask_kernel(const float* __restrict__ fw,
                                                   const float* __restrict__ gum,
                                                   float* __restrict__ out) {
    const int t = threadIdx.x;
    const int g = t >> 6;
    const int j = t & 63;
    const int bi = blockIdx.x * 4 + g;
    const int b = bi >> 6;
    const int i = bi & 63;

    const float f0 = fw[0], f1 = fw[1], f2 = fw[2];
    const float m = fmaxf(f0, fmaxf(f1, f2));
    const float e0 = expf(f0 - m), e1 = expf(f1 - m), e2 = expf(f2 - m);
    const float inv = 1.0f / (e0 + e1 + e2);
    const float w0 = e0 * inv, w1 = e1 * inv, w2 = e2 * inv;

    const float dsum = g_dist[0][b][i][j] * w0
                     + g_dist[1][b][i][j] * w1
                     + g_dist[2][b][i][j] * w2;

    const float e = 1.0f / (dsum + 1e-10f);
    const float emask = (j == i) ? 0.0f : e;

    __shared__ float red[8];
    float v = emask;
    #pragma unroll
    for (int o = 16; o; o >>= 1) v = fmaxf(v, __shfl_xor_sync(0xffffffffu, v, o));
    if ((t & 31) == 0) red[t >> 5] = v;
    __syncthreads();
    const float emax = fmaxf(red[2 * g], red[2 * g + 1]);

    float p = emask / emax;
    p = (j == i) ? 0.99f : p * 0.99f;

    const float l0 = logf(p / (1.0f - p));
    const float l1 = logf((1.0f - p) / p);

    const size_t gidx = ((size_t)(b * 4096 + i * 64 + j)) * 2;
    const float y0 = l0 + gum[gidx + 0];
    const float y1 = l1 + gum[gidx + 1];

    out[b * 4096 + i * 64 + j] = (y0 >= y1) ? 1.0f : 0.0f;
}

// ---------------------------------------------------------------------------
extern "C" void kernel_launch(void* const* d_in, const int* in_sizes, int n_in,
                              void* d_out, int out_size) {
    const float* X   = (const float*)d_in[0];
    const float* A0  = (const float*)d_in[1];
    const float* A1  = (const float*)d_in[2];
    const float* A2  = (const float*)d_in[3];
    const float* fw  = (const float*)d_in[4];
    const float* gum = (const float*)d_in[5];
    float* out = (float*)d_out;

    aprep_kernel<<<dim3(DPAD, 3), 128>>>(A0, A1, A2);
    fft_kernel<<<NROWS, 256>>>(X);

    const int smem2 = GEMM_SMEM_BF * (int)sizeof(__nv_bfloat16);   // 53760 B
    cudaFuncSetAttribute(gemm_mma_kernel,
                         cudaFuncAttributeMaxDynamicSharedMemorySize, smem2);
    gemm_mma_kernel<<<dim3(4, 16, 3), 256, smem2>>>();

    const int smem3 = SKP * TSP * sizeof(float)
                    + 3 * 256 * 8 * sizeof(unsigned long long);
    cudaFuncSetAttribute(gram_dist_kernel,
                         cudaFuncAttributeMaxDynamicSharedMemorySize, smem3);
    gram_dist_kernel<<<dim3(NB, 3), 1024, smem3>>>();

    mask_kernel<<<512, 256>>>(fw, gum, out);
}

// round 11
// speedup vs baseline: 1.4814x; 1.4814x over previous
#include <cuda_runtime.h>
#include <math.h>
#include <stdint.h>

#define NB 32
#define NC 64
#define NL 2048
#define S0 341
#define S1 341
#define S2 343
#define SKP 352      // padded K stride
#define TSP 68       // gram transposed-smem row stride (64 + 4)
#define NROWS 2048   // NB * NC

// Scratch (device globals; allocation-free per harness rules)
__device__ float g_bands[3][NROWS][SKP];
__device__ float g_Y[3][NROWS][SKP];
__device__ float g_dist[3][NB][NC][NC];

// ---------------------------------------------------------------------------
// f32x2 helpers (Blackwell packed fp32: FFMA2)
// ---------------------------------------------------------------------------
__device__ __forceinline__ unsigned long long pk2(float lo, float hi) {
    unsigned long long r;
    asm("mov.b64 %0, {%1, %2};" : "=l"(r) : "f"(lo), "f"(hi));
    return r;
}
__device__ __forceinline__ void fma2(unsigned long long& d,
                                     unsigned long long a, unsigned long long b) {
    asm("fma.rn.f32x2 %0, %1, %2, %0;" : "+l"(d) : "l"(a), "l"(b));
}
__device__ __forceinline__ void add2(unsigned long long& d, unsigned long long a) {
    asm("add.rn.f32x2 %0, %0, %1;" : "+l"(d) : "l"(a));
}
__device__ __forceinline__ float2 upk2(unsigned long long v) {
    float lo, hi;
    asm("mov.b64 {%0, %1}, %2;" : "=f"(lo), "=f"(hi) : "l"(v));
    return make_float2(lo, hi);
}

// ---------------------------------------------------------------------------
// Kernel 1: rfft magnitude via real-packed 1024-pt radix-4 FFT (R8 version)
// ---------------------------------------------------------------------------
__device__ __forceinline__ unsigned drev10(unsigned n) {
    unsigned r = __brev(n) >> 22;
    return ((r & 0x155u) << 1) | ((r >> 1) & 0x155u);
}

__global__ __launch_bounds__(256) void fft_kernel(const float* __restrict__ X) {
    __shared__ float sre[1024], sim[1024], wre[1025], wim[1025];
    const int row = blockIdx.x;
    const int t = threadIdx.x;
    const float2* x2 = (const float2*)(X + (size_t)row * NL);

    #pragma unroll
    for (int m = 0; m < 4; m++) {
        const int i = t + m * 256;
        float sn, cs;
        sincospif((float)i * (1.0f / 512.0f), &sn, &cs);
        wre[i] = cs;
        wim[i] = -sn;
        const float2 v = x2[i];
        const unsigned dr = drev10((unsigned)i);
        sre[dr] = v.x;
        sim[dr] = v.y;
    }
    if (t == 0) { wre[1024] = -1.0f; wim[1024] = 0.0f; }
    __syncthreads();

    {
        float4 xr = *(float4*)&sre[4 * t];
        float4 xi = *(float4*)&sim[4 * t];
        const float s02r = xr.x + xr.z, s02i = xi.x + xi.z;
        const float d02r = xr.x - xr.z, d02i = xi.x - xi.z;
        const float s13r = xr.y + xr.w, s13i = xi.y + xi.w;
        const float d13r = xr.y - xr.w, d13i = xi.y - xi.w;
        float4 yr, yi;
        yr.x = s02r + s13r;  yi.x = s02i + s13i;
        yr.y = d02r + d13i;  yi.y = d02i - d13r;
        yr.z = s02r - s13r;  yi.z = s02i - s13i;
        yr.w = d02r - d13i;  yi.w = d02i + d13r;
        *(float4*)&sre[4 * t] = yr;
        *(float4*)&sim[4 * t] = yi;
    }
    __syncthreads();

    #pragma unroll
    for (int s = 2; s <= 5; s++) {
        const int mm = 1 << (2 * (s - 1));
        const int j = t & (mm - 1);
        const int base = ((t >> (2 * (s - 1))) << (2 * s)) + j;
        const int r1 = j << (10 - 2 * s);

        const float x0r = sre[base],          x0i = sim[base];
        const float x1r = sre[base + mm],     x1i = sim[base + mm];
        const float x2r = sre[base + 2 * mm], x2i = sim[base + 2 * mm];
        const float x3r = sre[base + 3 * mm], x3i = sim[base + 3 * mm];
        const float w1r = wre[r1],     w1i = wim[r1];
        const float w2r = wre[2 * r1], w2i = wim[2 * r1];
        const float w3r = wre[3 * r1], w3i = wim[3 * r1];

        const float u1r = x1r * w1r - x1i * w1i, u1i = x1r * w1i + x1i * w1r;
        const float u2r = x2r * w2r - x2i * w2i, u2i = x2r * w2i + x2i * w2r;
        const float u3r = x3r * w3r - x3i * w3i, u3i = x3r * w3i + x3i * w3r;

        const float s02r = x0r + u2r, s02i = x0i + u2i;
        const float d02r = x0r - u2r, d02i = x0i - u2i;
        const float s13r = u1r + u3r, s13i = u1i + u3i;
        const float d13r = u1r - u3r, d13i = u1i - u3i;

        sre[base]          = s02r + s13r;  sim[base]          = s02i + s13i;
        sre[base + mm]     = d02r + d13i;  sim[base + mm]     = d02i - d13r;
        sre[base + 2 * mm] = s02r - s13r;  sim[base + 2 * mm] = s02i - s13i;
        sre[base + 3 * mm] = d02r - d13i;  sim[base + 3 * mm] = d02i + d13r;
        __syncthreads();
    }

    const float CR = 0.999995293809576f;
    const float CI = -0.003067956762966f;
    for (int pos = t; pos < 3 * SKP; pos += 256) {
        int band, off, k, sk;
        if (pos < SKP)            { band = 0; off = pos;           k = off;       sk = S0; }
        else if (pos < 2 * SKP)   { band = 1; off = pos - SKP;     k = S0 + off;  sk = S1; }
        else                      { band = 2; off = pos - 2 * SKP; k = 682 + off; sk = S2; }
        float mag = 0.0f;
        if (off < sk) {
            const int ka = k & 1023;
            const int kb = (1024 - k) & 1023;
            const float z1r = sre[ka], z1i = sim[ka];
            const float z2r = sre[kb], z2i = sim[kb];
            const float zer = z1r + z2r, zei = z1i - z2i;
            const float zor = z1i + z2i, zoi = z2r - z1r;
            const int m = k >> 1;
            float cs = wre[m], msn = wim[m];
            if (k & 1) {
                const float c2 = cs * CR - msn * CI;
                msn = cs * CI + msn * CR;
                cs = c2;
            }
            const float xr = zer + cs * zor - msn * zoi;
            const float xi = zei + cs * zoi + msn * zor;
            mag = 0.5f * sqrtf(xr * xr + xi * xi);
        }
        (&g_bands[0][0][0])[((size_t)band * NROWS + row) * SKP + off] = mag;
    }
}

// ---------------------------------------------------------------------------
// Kernel 2: Y[k][r][d] = sum_s band[k][r][s] * A_k[d][s]
// 128x128 tiles, 256 threads, 8x8 per-thread (row-paired f32x2): halves
// smem wavefronts per MAC vs 8x4. grid (3, 16, 3) = 144 blocks (one wave).
// ---------------------------------------------------------------------------
__global__ __launch_bounds__(256) void gemm_kernel(const float* __restrict__ A0,
                                                   const float* __restrict__ A1,
                                                   const float* __restrict__ A2) {
    __shared__ float Xs[2][16][128];
    __shared__ float As[2][16][128];

    const int k = blockIdx.z;
    const int sk = (k == 2) ? S2 : S0;
    const float* A = (k == 0) ? A0 : ((k == 1) ? A1 : A2);
    const int n0 = blockIdx.x * 128;
    const int r0 = blockIdx.y * 128;
    const int t = threadIdx.x;
    const int tx = t & 15;      // d tile: 8 cols
    const int ty = t >> 4;      // r tile: 8 rows (4 pairs)
    const float* band = &g_bands[k][0][0];

    const int lr = t & 127;          // loader row
    const int lh = (t >> 7) * 8;     // loader k-offset 0/8

    const int ad = n0 + lr;
    const bool dok = ad < sk;
    const float* arow = A + (size_t)ad * sk;

    // acc[p][c]: lo = Y[r0+ty*8+2p][n0+tx*8+c], hi = row +1
    unsigned long long acc[4][8];
    #pragma unroll
    for (int p = 0; p < 4; p++)
        #pragma unroll
        for (int c = 0; c < 8; c++) acc[p][c] = 0ull;

    float4 bx0, bx1, ba0, ba1;

#define LDG_TILE(kt)                                                            \
    do {                                                                        \
        const float* xp = &band[(size_t)(r0 + lr) * SKP + (kt) + lh];           \
        bx0 = *(const float4*)xp;  bx1 = *(const float4*)(xp + 4);              \
        const int s_ = (kt) + lh;                                               \
        ba0.x = (dok && s_ + 0 < sk) ? arow[s_ + 0] : 0.0f;                     \
        ba0.y = (dok && s_ + 1 < sk) ? arow[s_ + 1] : 0.0f;                     \
        ba0.z = (dok && s_ + 2 < sk) ? arow[s_ + 2] : 0.0f;                     \
        ba0.w = (dok && s_ + 3 < sk) ? arow[s_ + 3] : 0.0f;                     \
        ba1.x = (dok && s_ + 4 < sk) ? arow[s_ + 4] : 0.0f;                     \
        ba1.y = (dok && s_ + 5 < sk) ? arow[s_ + 5] : 0.0f;                     \
        ba1.z = (dok && s_ + 6 < sk) ? arow[s_ + 6] : 0.0f;                     \
        ba1.w = (dok && s_ + 7 < sk) ? arow[s_ + 7] : 0.0f;                     \
    } while (0)

#define STS_TILE(buf)                                                           \
    do {                                                                        \
        Xs[buf][lh + 0][lr] = bx0.x;  Xs[buf][lh + 1][lr] = bx0.y;              \
        Xs[buf][lh + 2][lr] = bx0.z;  Xs[buf][lh + 3][lr] = bx0.w;              \
        Xs[buf][lh + 4][lr] = bx1.x;  Xs[buf][lh + 5][lr] = bx1.y;              \
        Xs[buf][lh + 6][lr] = bx1.z;  Xs[buf][lh + 7][lr] = bx1.w;              \
        As[buf][lh + 0][lr] = ba0.x;  As[buf][lh + 1][lr] = ba0.y;              \
        As[buf][lh + 2][lr] = ba0.z;  As[buf][lh + 3][lr] = ba0.w;              \
        As[buf][lh + 4][lr] = ba1.x;  As[buf][lh + 5][lr] = ba1.y;              \
        As[buf][lh + 6][lr] = ba1.z;  As[buf][lh + 7][lr] = ba1.w;              \
    } while (0)

    LDG_TILE(0);
    STS_TILE(0);
    __syncthreads();

    const int NT = SKP / 16;  // 22
    for (int kt = 0; kt < NT; kt++) {
        const int buf = kt & 1;
        if (kt + 1 < NT) LDG_TILE((kt + 1) * 16);

        #pragma unroll
        for (int kk = 0; kk < 16; kk++) {
            const ulonglong2 a01 = *(const ulonglong2*)&Xs[buf][kk][ty * 8];
            const ulonglong2 a23 = *(const ulonglong2*)&Xs[buf][kk][ty * 8 + 4];
            const float4 b0 = *(const float4*)&As[buf][kk][tx * 8];
            const float4 b1 = *(const float4*)&As[buf][kk][tx * 8 + 4];
            unsigned long long bd[8];
            bd[0] = pk2(b0.x, b0.x);  bd[1] = pk2(b0.y, b0.y);
            bd[2] = pk2(b0.z, b0.z);  bd[3] = pk2(b0.w, b0.w);
            bd[4] = pk2(b1.x, b1.x);  bd[5] = pk2(b1.y, b1.y);
            bd[6] = pk2(b1.z, b1.z);  bd[7] = pk2(b1.w, b1.w);
            const unsigned long long ap[4] = {a01.x, a01.y, a23.x, a23.y};
            #pragma unroll
            for (int p = 0; p < 4; p++)
                #pragma unroll
                for (int c = 0; c < 8; c++)
                    fma2(acc[p][c], ap[p], bd[c]);
        }
        if (kt + 1 < NT) STS_TILE(buf ^ 1);
        __syncthreads();
    }

    // epilogue: row-pair accs -> g_Y; guard col chunks beyond 352
    const int nb = n0 + tx * 8;
    #pragma unroll
    for (int p = 0; p < 4; p++) {
        const int r = r0 + ty * 8 + 2 * p;
        float lo[8], hi[8];
        #pragma unroll
        for (int c = 0; c < 8; c++) {
            const float2 v = upk2(acc[p][c]);
            lo[c] = v.x; hi[c] = v.y;
        }
        if (nb < SKP) {
            *(float4*)&g_Y[k][r][nb]     = make_float4(lo[0], lo[1], lo[2], lo[3]);
            *(float4*)&g_Y[k][r + 1][nb] = make_float4(hi[0], hi[1], hi[2], hi[3]);
        }
        if (nb + 4 < SKP) {
            *(float4*)&g_Y[k][r][nb + 4]     = make_float4(lo[4], lo[5], lo[6], lo[7]);
            *(float4*)&g_Y[k][r + 1][nb + 4] = make_float4(hi[4], hi[5], hi[6], hi[7]);
        }
    }
#undef LDG_TILE
#undef STS_TILE
}

// ---------------------------------------------------------------------------
// Kernel 3: per (batch b, band k): dist = relu(q_i + q_j - 2 * Yi.Yj)
// 512 threads = 8 K-groups x 64 threads; each thread an 8x8 tile (row-paired
// f32x2) over 44 d-values -> halved smem bytes/MAC. Tree reduction.
// grid (32, 3). Dynamic smem: sYT[352*68] f32 + part[4][64][32] ull.
// ---------------------------------------------------------------------------
__global__ __launch_bounds__(512) void gram_dist_kernel() {
    extern __shared__ float smemf[];
    float* sYT = smemf;                                             // 352*TSP
    unsigned long long* part = (unsigned long long*)(smemf + SKP * TSP); // [4][64][32]
    __shared__ float q[64];

    const int b = blockIdx.x;
    const int k = blockIdx.y;
    const int t = threadIdx.x;

    // load + transpose: g_Y[k][b*64 + r][*] -> sYT[d][r]
    {
        const int r_ = t & 7;
        const int c4_ = t >> 3;      // 0..63
        const float* src = &g_Y[k][b * 64][0];
        #pragma unroll
        for (int rb = 0; rb < 64; rb += 8) {
            const int r = rb + r_;
            #pragma unroll
            for (int cc = 0; cc < 2; cc++) {
                const int c4 = c4_ + 64 * cc;
                if (c4 < SKP / 4) {
                    const float4 v = *(const float4*)&src[(size_t)r * SKP + c4 * 4];
                    const int d = c4 * 4;
                    sYT[(d + 0) * TSP + r] = v.x;
                    sYT[(d + 1) * TSP + r] = v.y;
                    sYT[(d + 2) * TSP + r] = v.z;
                    sYT[(d + 3) * TSP + r] = v.w;
                }
            }
        }
    }
    __syncthreads();

    const int g = t >> 6;          // K-group 0..7
    const int tg = t & 63;
    const int ty = tg >> 3;        // 8x8 thread grid
    const int tx = tg & 7;
    const int ti = ty * 8;
    const int tj = tx * 8;

    // acc[p][c]: lo = G[ti+2p][tj+c], hi = G[ti+2p+1][tj+c]
    unsigned long long acc[4][8];
    #pragma unroll
    for (int p = 0; p < 4; p++)
        #pragma unroll
        for (int c = 0; c < 8; c++) acc[p][c] = 0ull;

    const float* base = &sYT[g * 44 * TSP];
    #pragma unroll 4
    for (int dd = 0; dd < 44; dd++) {
        const float* rowp = base + dd * TSP;
        const ulonglong2 a01 = *(const ulonglong2*)&rowp[ti];
        const ulonglong2 a23 = *(const ulonglong2*)&rowp[ti + 4];
        const float4 b0 = *(const float4*)&rowp[tj];
        const float4 b1 = *(const float4*)&rowp[tj + 4];
        unsigned long long bd[8];
        bd[0] = pk2(b0.x, b0.x);  bd[1] = pk2(b0.y, b0.y);
        bd[2] = pk2(b0.z, b0.z);  bd[3] = pk2(b0.w, b0.w);
        bd[4] = pk2(b1.x, b1.x);  bd[5] = pk2(b1.y, b1.y);
        bd[6] = pk2(b1.z, b1.z);  bd[7] = pk2(b1.w, b1.w);
        const unsigned long long ap[4] = {a01.x, a01.y, a23.x, a23.y};
        #pragma unroll
        for (int p = 0; p < 4; p++)
            #pragma unroll
            for (int c = 0; c < 8; c++)
                fma2(acc[p][c], ap[p], bd[c]);
    }

    // tree reduction across the 8 K-groups: 8 -> 4 -> 2 -> 1
    unsigned long long* my = &part[(size_t)(g & 3) * 64 * 32 + (size_t)tg * 32];
    __syncthreads();
    if (g >= 4) {
        #pragma unroll
        for (int p = 0; p < 4; p++)
            #pragma unroll
            for (int c = 0; c < 8; c++) my[p * 8 + c] = acc[p][c];
    }
    __syncthreads();
    if (g < 4) {
        #pragma unroll
        for (int p = 0; p < 4; p++)
            #pragma unroll
            for (int c = 0; c < 8; c++) add2(acc[p][c], my[p * 8 + c]);
    }
    __syncthreads();
    if (g == 2 || g == 3) {
        unsigned long long* dst = &part[(size_t)(g - 2) * 64 * 32 + (size_t)tg * 32];
        #pragma unroll
        for (int p = 0; p < 4; p++)
            #pragma unroll
            for (int c = 0; c < 8; c++) dst[p * 8 + c] = acc[p][c];
    }
    __syncthreads();
    if (g < 2) {
        #pragma unroll
        for (int p = 0; p < 4; p++)
            #pragma unroll
            for (int c = 0; c < 8; c++) add2(acc[p][c], my[p * 8 + c]);
    }
    __syncthreads();
    if (g == 1) {
        unsigned long long* dst = &part[(size_t)tg * 32];
        #pragma unroll
        for (int p = 0; p < 4; p++)
            #pragma unroll
            for (int c = 0; c < 8; c++) dst[p * 8 + c] = acc[p][c];
    }
    __syncthreads();
    if (g == 0) {
        #pragma unroll
        for (int p = 0; p < 4; p++)
            #pragma unroll
            for (int c = 0; c < 8; c++) add2(acc[p][c], my[p * 8 + c]);
        // q_i = G_ii from diagonal tiles (diagonal masked downstream)
        if (ty == tx) {
            #pragma unroll
            for (int i = 0; i < 8; i++) {
                const float2 v = upk2(acc[i >> 1][i]);
                q[ti + i] = (i & 1) ? v.y : v.x;
            }
        }
    }
    __syncthreads();

    if (g == 0) {
        float qj[8];
        #pragma unroll
        for (int c = 0; c < 8; c++) qj[c] = q[tj + c];
        #pragma unroll
        for (int p = 0; p < 4; p++) {
            const int r = ti + 2 * p;
            const float qlo = q[r], qhi = q[r + 1];
            float lo[8], hi[8];
            #pragma unroll
            for (int c = 0; c < 8; c++) {
                const float2 v = upk2(acc[p][c]);
                lo[c] = fmaxf(qlo + qj[c] - 2.0f * v.x, 0.0f);
                hi[c] = fmaxf(qhi + qj[c] - 2.0f * v.y, 0.0f);
            }
            *(float4*)&g_dist[k][b][r][tj]         = make_float4(lo[0], lo[1], lo[2], lo[3]);
            *(float4*)&g_dist[k][b][r][tj + 4]     = make_float4(lo[4], lo[5], lo[6], lo[7]);
            *(float4*)&g_dist[k][b][r + 1][tj]     = make_float4(hi[0], hi[1], hi[2], hi[3]);
            *(float4*)&g_dist[k][b][r + 1][tj + 4] = make_float4(hi[4], hi[5], hi[6], hi[7]);
        }
    }
}

// ---------------------------------------------------------------------------
// Kernel 4: mask (unchanged)
// ---------------------------------------------------------------------------
__global__ __launch_bounds__(256) void mask_kernel(const float* __restrict__ fw,
                                                   const float* __restrict__ gum,
                                                   float* __restrict__ out) {
    const int t = threadIdx.x;
    const int g = t >> 6;
    const int j = t & 63;
    const int bi = blockIdx.x * 4 + g;
    const int b = bi >> 6;
    const int i = bi & 63;

    const float f0 = fw[0], f1 = fw[1], f2 = fw[2];
    const float m = fmaxf(f0, fmaxf(f1, f2));
    const float e0 = expf(f0 - m), e1 = expf(f1 - m), e2 = expf(f2 - m);
    const float inv = 1.0f / (e0 + e1 + e2);
    const float w0 = e0 * inv, w1 = e1 * inv, w2 = e2 * inv;

    const float dsum = g_dist[0][b][i][j] * w0
                     + g_dist[1][b][i][j] * w1
                     + g_dist[2][b][i][j] * w2;

    const float e = 1.0f / (dsum + 1e-10f);
    const float emask = (j == i) ? 0.0f : e;

    __shared__ float red[8];
    float v = emask;
    #pragma unroll
    for (int o = 16; o; o >>= 1) v = fmaxf(v, __shfl_xor_sync(0xffffffffu, v, o));
    if ((t & 31) == 0) red[t >> 5] = v;
    __syncthreads();
    const float emax = fmaxf(red[2 * g], red[2 * g + 1]);

    float p = emask / emax;
    p = (j == i) ? 0.99f : p * 0.99f;

    const float l0 = logf(p / (1.0f - p));
    const float l1 = logf((1.0f - p) / p);

    const size_t gidx = ((size_t)(b * 4096 + i * 64 + j)) * 2;
    const float y0 = l0 + gum[gidx + 0];
    const float y1 = l1 + gum[gidx + 1];

    out[b * 4096 + i * 64 + j] = (y0 >= y1) ? 1.0f : 0.0f;
}

// ---------------------------------------------------------------------------
extern "C" void kernel_launch(void* const* d_in, const int* in_sizes, int n_in,
                              void* d_out, int out_size) {
    const float* X   = (const float*)d_in[0];
    const float* A0  = (const float*)d_in[1];
    const float* A1  = (const float*)d_in[2];
    const float* A2  = (const float*)d_in[3];
    const float* fw  = (const float*)d_in[4];
    const float* gum = (const float*)d_in[5];
    float* out = (float*)d_out;

    fft_kernel<<<NROWS, 256>>>(X);
    gemm_kernel<<<dim3(3, 16, 3), 256>>>(A0, A1, A2);

    const int smem3 = SKP * TSP * sizeof(float)
                    + 4 * 64 * 32 * sizeof(unsigned long long);   // 95.7KB + 64KB
    cudaFuncSetAttribute(gram_dist_kernel,
                         cudaFuncAttributeMaxDynamicSharedMemorySize, smem3);
    gram_dist_kernel<<<dim3(NB, 3), 512, smem3>>>();

    mask_kernel<<<512, 256>>>(fw, gum, out);
}

// round 12
// speedup vs baseline: 1.5513x; 1.0472x over previous
#include <cuda_runtime.h>
#include <math.h>
#include <stdint.h>

#define NB 32
#define NC 64
#define NL 2048
#define S0 341
#define S1 341
#define S2 343
#define SKP 352      // padded K stride
#define TSP 68       // gram transposed-smem row stride (64 + 4)
#define NROWS 2048   // NB * NC

// Scratch (device globals; allocation-free per harness rules)
__device__ float g_bands[3][NROWS][SKP];
__device__ float g_Y[3][NROWS][SKP];
__device__ float g_dist[3][NB][NC][NC];
__device__ float2 g_tw[1025];          // twiddle LUT: e^{-i*pi*j/512}

// ---------------------------------------------------------------------------
// f32x2 helpers (Blackwell packed fp32: FFMA2)
// ---------------------------------------------------------------------------
__device__ __forceinline__ unsigned long long pk2(float lo, float hi) {
    unsigned long long r;
    asm("mov.b64 %0, {%1, %2};" : "=l"(r) : "f"(lo), "f"(hi));
    return r;
}
__device__ __forceinline__ void fma2(unsigned long long& d,
                                     unsigned long long a, unsigned long long b) {
    asm("fma.rn.f32x2 %0, %1, %2, %0;" : "+l"(d) : "l"(a), "l"(b));
}
__device__ __forceinline__ void add2(unsigned long long& d, unsigned long long a) {
    asm("add.rn.f32x2 %0, %0, %1;" : "+l"(d) : "l"(a));
}
__device__ __forceinline__ float2 upk2(unsigned long long v) {
    float lo, hi;
    asm("mov.b64 {%0, %1}, %2;" : "=f"(lo), "=f"(hi) : "l"(v));
    return make_float2(lo, hi);
}

// ---------------------------------------------------------------------------
// Kernel 0: build twiddle LUT once (1 block)
// ---------------------------------------------------------------------------
__global__ __launch_bounds__(256) void twinit_kernel() {
    for (int i = threadIdx.x; i < 1025; i += 256) {
        float sn, cs;
        sincospif((float)i * (1.0f / 512.0f), &sn, &cs);
        g_tw[i] = make_float2(cs, -sn);
    }
}

// ---------------------------------------------------------------------------
// Kernel 1: rfft magnitude via real-packed 1024-pt radix-4 FFT
// twiddles loaded from gmem LUT (L2-resident) instead of sincospif per block
// ---------------------------------------------------------------------------
__device__ __forceinline__ unsigned drev10(unsigned n) {
    unsigned r = __brev(n) >> 22;
    return ((r & 0x155u) << 1) | ((r >> 1) & 0x155u);
}

__global__ __launch_bounds__(256) void fft_kernel(const float* __restrict__ X) {
    __shared__ float sre[1024], sim[1024], wre[1025], wim[1025];
    const int row = blockIdx.x;
    const int t = threadIdx.x;
    const float2* x2 = (const float2*)(X + (size_t)row * NL);

    #pragma unroll
    for (int m = 0; m < 4; m++) {
        const int i = t + m * 256;
        const float2 w = g_tw[i];
        wre[i] = w.x;
        wim[i] = w.y;
        const float2 v = x2[i];       // z[i] = x[2i] + i*x[2i+1]
        const unsigned dr = drev10((unsigned)i);
        sre[dr] = v.x;
        sim[dr] = v.y;
    }
    if (t == 0) { wre[1024] = -1.0f; wim[1024] = 0.0f; }
    __syncthreads();

    // stage 1 (m=1): contiguous quads, twiddle = 1, float4 access
    {
        float4 xr = *(float4*)&sre[4 * t];
        float4 xi = *(float4*)&sim[4 * t];
        const float s02r = xr.x + xr.z, s02i = xi.x + xi.z;
        const float d02r = xr.x - xr.z, d02i = xi.x - xi.z;
        const float s13r = xr.y + xr.w, s13i = xi.y + xi.w;
        const float d13r = xr.y - xr.w, d13i = xi.y - xi.w;
        float4 yr, yi;
        yr.x = s02r + s13r;  yi.x = s02i + s13i;
        yr.y = d02r + d13i;  yi.y = d02i - d13r;
        yr.z = s02r - s13r;  yi.z = s02i - s13i;
        yr.w = d02r - d13i;  yi.w = d02i + d13r;
        *(float4*)&sre[4 * t] = yr;
        *(float4*)&sim[4 * t] = yi;
    }
    __syncthreads();

    // stages 2..5
    #pragma unroll
    for (int s = 2; s <= 5; s++) {
        const int mm = 1 << (2 * (s - 1));
        const int j = t & (mm - 1);
        const int base = ((t >> (2 * (s - 1))) << (2 * s)) + j;
        const int r1 = j << (10 - 2 * s);

        const float x0r = sre[base],          x0i = sim[base];
        const float x1r = sre[base + mm],     x1i = sim[base + mm];
        const float x2r = sre[base + 2 * mm], x2i = sim[base + 2 * mm];
        const float x3r = sre[base + 3 * mm], x3i = sim[base + 3 * mm];
        const float w1r = wre[r1],     w1i = wim[r1];
        const float w2r = wre[2 * r1], w2i = wim[2 * r1];
        const float w3r = wre[3 * r1], w3i = wim[3 * r1];

        const float u1r = x1r * w1r - x1i * w1i, u1i = x1r * w1i + x1i * w1r;
        const float u2r = x2r * w2r - x2i * w2i, u2i = x2r * w2i + x2i * w2r;
        const float u3r = x3r * w3r - x3i * w3i, u3i = x3r * w3i + x3i * w3r;

        const float s02r = x0r + u2r, s02i = x0i + u2i;
        const float d02r = x0r - u2r, d02i = x0i - u2i;
        const float s13r = u1r + u3r, s13i = u1i + u3i;
        const float d13r = u1r - u3r, d13i = u1i - u3i;

        sre[base]          = s02r + s13r;  sim[base]          = s02i + s13i;
        sre[base + mm]     = d02r + d13i;  sim[base + mm]     = d02i - d13r;
        sre[base + 2 * mm] = s02r - s13r;  sim[base + 2 * mm] = s02i - s13i;
        sre[base + 3 * mm] = d02r - d13i;  sim[base + 3 * mm] = d02i + d13r;
        __syncthreads();
    }

    // untangle real-packed spectrum + magnitude -> zero-padded band slabs
    const float CR = 0.999995293809576f;    // cos(pi/1024)
    const float CI = -0.003067956762966f;   // -sin(pi/1024)
    for (int pos = t; pos < 3 * SKP; pos += 256) {
        int band, off, k, sk;
        if (pos < SKP)            { band = 0; off = pos;           k = off;       sk = S0; }
        else if (pos < 2 * SKP)   { band = 1; off = pos - SKP;     k = S0 + off;  sk = S1; }
        else                      { band = 2; off = pos - 2 * SKP; k = 682 + off; sk = S2; }
        float mag = 0.0f;
        if (off < sk) {
            const int ka = k & 1023;
            const int kb = (1024 - k) & 1023;
            const float z1r = sre[ka], z1i = sim[ka];
            const float z2r = sre[kb], z2i = sim[kb];
            const float zer = z1r + z2r, zei = z1i - z2i;        // 2*Ze
            const float zor = z1i + z2i, zoi = z2r - z1r;        // 2*Zo
            const int m = k >> 1;
            float cs = wre[m], msn = wim[m];                     // e^{-i*pi*m/512}
            if (k & 1) {
                const float c2 = cs * CR - msn * CI;
                msn = cs * CI + msn * CR;
                cs = c2;
            }
            const float xr = zer + cs * zor - msn * zoi;
            const float xi = zei + cs * zoi + msn * zor;
            mag = 0.5f * sqrtf(xr * xr + xi * xi);
        }
        (&g_bands[0][0][0])[((size_t)band * NROWS + row) * SKP + off] = mag;
    }
}

// ---------------------------------------------------------------------------
// Kernel 2: Y[k][r][d] = sum_s band[k][r][s] * A_k[d][s]   (R8 version)
// 128(r) x 64(d) tiles, 256 threads, 8x4 row-paired f32x2. grid (6, 16, 3)
// ---------------------------------------------------------------------------
__global__ __launch_bounds__(256) void gemm_kernel(const float* __restrict__ A0,
                                                   const float* __restrict__ A1,
                                                   const float* __restrict__ A2) {
    __shared__ float Xs[2][16][128];
    __shared__ float As[2][16][64];

    const int k = blockIdx.z;
    const int sk = (k == 2) ? S2 : S0;
    const float* A = (k == 0) ? A0 : ((k == 1) ? A1 : A2);
    const int d0 = blockIdx.x * 64;
    const int r0 = blockIdx.y * 128;
    const int t = threadIdx.x;
    const int tx = t & 15;      // d group: 4 cols
    const int ty = t >> 4;      // r group: 8 rows (4 pairs)
    const float* band = &g_bands[k][0][0];

    const int xlr = t & 127;
    const int xlh = (t >> 7) * 8;
    const int alr = t & 63;
    const int alh = (t >> 6) * 4;

    const int ad = d0 + alr;
    const bool dok = ad < sk;
    const float* arow = A + (size_t)ad * sk;

    unsigned long long acc[4][4];
    #pragma unroll
    for (int p = 0; p < 4; p++)
        #pragma unroll
        for (int j = 0; j < 4; j++) acc[p][j] = 0ull;

    float4 bx0, bx1, ba0;

#define LDG_TILE(kt)                                                            \
    do {                                                                        \
        const float* xp = &band[(size_t)(r0 + xlr) * SKP + (kt) + xlh];         \
        bx0 = *(const float4*)xp;  bx1 = *(const float4*)(xp + 4);              \
        const int s_ = (kt) + alh;                                              \
        ba0.x = (dok && s_ + 0 < sk) ? arow[s_ + 0] : 0.0f;                     \
        ba0.y = (dok && s_ + 1 < sk) ? arow[s_ + 1] : 0.0f;                     \
        ba0.z = (dok && s_ + 2 < sk) ? arow[s_ + 2] : 0.0f;                     \
        ba0.w = (dok && s_ + 3 < sk) ? arow[s_ + 3] : 0.0f;                     \
    } while (0)

#define STS_TILE(buf)                                                           \
    do {                                                                        \
        Xs[buf][xlh + 0][xlr] = bx0.x;  Xs[buf][xlh + 1][xlr] = bx0.y;          \
        Xs[buf][xlh + 2][xlr] = bx0.z;  Xs[buf][xlh + 3][xlr] = bx0.w;          \
        Xs[buf][xlh + 4][xlr] = bx1.x;  Xs[buf][xlh + 5][xlr] = bx1.y;          \
        Xs[buf][xlh + 6][xlr] = bx1.z;  Xs[buf][xlh + 7][xlr] = bx1.w;          \
        As[buf][alh + 0][alr] = ba0.x;  As[buf][alh + 1][alr] = ba0.y;          \
        As[buf][alh + 2][alr] = ba0.z;  As[buf][alh + 3][alr] = ba0.w;          \
    } while (0)

    LDG_TILE(0);
    STS_TILE(0);
    __syncthreads();

    const int NT = SKP / 16;  // 22
    for (int kt = 0; kt < NT; kt++) {
        const int buf = kt & 1;
        if (kt + 1 < NT) LDG_TILE((kt + 1) * 16);

        #pragma unroll
        for (int kk = 0; kk < 16; kk++) {
            const ulonglong2 a01 = *(const ulonglong2*)&Xs[buf][kk][ty * 8];
            const ulonglong2 a23 = *(const ulonglong2*)&Xs[buf][kk][ty * 8 + 4];
            const float4 b = *(const float4*)&As[buf][kk][tx * 4];
            const unsigned long long bd0 = pk2(b.x, b.x);
            const unsigned long long bd1 = pk2(b.y, b.y);
            const unsigned long long bd2 = pk2(b.z, b.z);
            const unsigned long long bd3 = pk2(b.w, b.w);
            fma2(acc[0][0], a01.x, bd0);  fma2(acc[0][1], a01.x, bd1);
            fma2(acc[0][2], a01.x, bd2);  fma2(acc[0][3], a01.x, bd3);
            fma2(acc[1][0], a01.y, bd0);  fma2(acc[1][1], a01.y, bd1);
            fma2(acc[1][2], a01.y, bd2);  fma2(acc[1][3], a01.y, bd3);
            fma2(acc[2][0], a23.x, bd0);  fma2(acc[2][1], a23.x, bd1);
            fma2(acc[2][2], a23.x, bd2);  fma2(acc[2][3], a23.x, bd3);
            fma2(acc[3][0], a23.y, bd0);  fma2(acc[3][1], a23.y, bd1);
            fma2(acc[3][2], a23.y, bd2);  fma2(acc[3][3], a23.y, bd3);
        }
        if (kt + 1 < NT) STS_TILE(buf ^ 1);
        __syncthreads();
    }

    const int d = d0 + tx * 4;
    if (d < SKP) {            // block d0=320 covers d up to 383
        #pragma unroll
        for (int p = 0; p < 4; p++) {
            const float2 v0 = upk2(acc[p][0]);
            const float2 v1 = upk2(acc[p][1]);
            const float2 v2 = upk2(acc[p][2]);
            const float2 v3 = upk2(acc[p][3]);
            const int r = r0 + ty * 8 + 2 * p;
            float4 lo = make_float4(v0.x, v1.x, v2.x, v3.x);
            float4 hi = make_float4(v0.y, v1.y, v2.y, v3.y);
            *(float4*)&g_Y[k][r][d]     = lo;
            *(float4*)&g_Y[k][r + 1][d] = hi;
        }
    }
#undef LDG_TILE
#undef STS_TILE
}

// ---------------------------------------------------------------------------
// Kernel 3: gram/dist (R8 version — 512 threads, 2-way K-split)
// ---------------------------------------------------------------------------
__global__ __launch_bounds__(512) void gram_dist_kernel() {
    extern __shared__ float smemf[];
    float* sYT = smemf;                                       // 352*TSP
    unsigned long long* part = (unsigned long long*)(smemf + SKP * TSP); // [256][8]
    __shared__ float q[64];

    const int b = blockIdx.x;
    const int k = blockIdx.y;
    const int t = threadIdx.x;

    {
        const int r_ = t & 7;
        const int c4_ = t >> 3;      // 0..63
        const float* src = &g_Y[k][b * 64][0];
        #pragma unroll
        for (int rb = 0; rb < 64; rb += 8) {
            const int r = rb + r_;
            #pragma unroll
            for (int cc = 0; cc < 2; cc++) {
                const int c4 = c4_ + 64 * cc;
                if (c4 < SKP / 4) {
                    const float4 v = *(const float4*)&src[(size_t)r * SKP + c4 * 4];
                    const int d = c4 * 4;
                    sYT[(d + 0) * TSP + r] = v.x;
                    sYT[(d + 1) * TSP + r] = v.y;
                    sYT[(d + 2) * TSP + r] = v.z;
                    sYT[(d + 3) * TSP + r] = v.w;
                }
            }
        }
    }
    __syncthreads();

    const int half = t >> 8;
    const int tt = t & 255;
    const int ty = tt >> 4;
    const int tx = tt & 15;
    const int ti = ty * 4;
    const int tj = tx * 4;

    unsigned long long acc[2][4];
    #pragma unroll
    for (int p = 0; p < 2; p++)
        #pragma unroll
        for (int j = 0; j < 4; j++) acc[p][j] = 0ull;

    const float* base = &sYT[half * 176 * TSP];
    ulonglong2 aC = *(const ulonglong2*)&base[ti];
    float4 bC = *(const float4*)&base[tj];

    #pragma unroll 4
    for (int dd = 0; dd < 175; dd++) {
        const float* nxt = base + (dd + 1) * TSP;
        const ulonglong2 aN = *(const ulonglong2*)&nxt[ti];
        const float4 bN = *(const float4*)&nxt[tj];

        const unsigned long long bd0 = pk2(bC.x, bC.x);
        const unsigned long long bd1 = pk2(bC.y, bC.y);
        const unsigned long long bd2 = pk2(bC.z, bC.z);
        const unsigned long long bd3 = pk2(bC.w, bC.w);
        fma2(acc[0][0], aC.x, bd0);  fma2(acc[0][1], aC.x, bd1);
        fma2(acc[0][2], aC.x, bd2);  fma2(acc[0][3], aC.x, bd3);
        fma2(acc[1][0], aC.y, bd0);  fma2(acc[1][1], aC.y, bd1);
        fma2(acc[1][2], aC.y, bd2);  fma2(acc[1][3], aC.y, bd3);

        aC = aN; bC = bN;
    }
    {
        const unsigned long long bd0 = pk2(bC.x, bC.x);
        const unsigned long long bd1 = pk2(bC.y, bC.y);
        const unsigned long long bd2 = pk2(bC.z, bC.z);
        const unsigned long long bd3 = pk2(bC.w, bC.w);
        fma2(acc[0][0], aC.x, bd0);  fma2(acc[0][1], aC.x, bd1);
        fma2(acc[0][2], aC.x, bd2);  fma2(acc[0][3], aC.x, bd3);
        fma2(acc[1][0], aC.y, bd0);  fma2(acc[1][1], aC.y, bd1);
        fma2(acc[1][2], aC.y, bd2);  fma2(acc[1][3], aC.y, bd3);
    }

    if (half == 1) {
        #pragma unroll
        for (int p = 0; p < 2; p++)
            #pragma unroll
            for (int j = 0; j < 4; j++) part[(size_t)tt * 8 + p * 4 + j] = acc[p][j];
    }
    __syncthreads();

    if (half == 0) {
        #pragma unroll
        for (int p = 0; p < 2; p++)
            #pragma unroll
            for (int j = 0; j < 4; j++) add2(acc[p][j], part[(size_t)tt * 8 + p * 4 + j]);

        if (ty == tx) {
            q[ti + 0] = upk2(acc[0][0]).x;
            q[ti + 1] = upk2(acc[0][1]).y;
            q[ti + 2] = upk2(acc[1][2]).x;
            q[ti + 3] = upk2(acc[1][3]).y;
        }
    }
    __syncthreads();

    if (half == 0) {
        #pragma unroll
        for (int p = 0; p < 2; p++) {
            const float2 g0 = upk2(acc[p][0]);
            const float2 g1 = upk2(acc[p][1]);
            const float2 g2 = upk2(acc[p][2]);
            const float2 g3 = upk2(acc[p][3]);
            const float qj0 = q[tj + 0], qj1 = q[tj + 1];
            const float qj2 = q[tj + 2], qj3 = q[tj + 3];
            const int r = ti + 2 * p;
            const float qlo = q[r], qhi = q[r + 1];
            float4 lo, hi;
            lo.x = fmaxf(qlo + qj0 - 2.0f * g0.x, 0.0f);
            lo.y = fmaxf(qlo + qj1 - 2.0f * g1.x, 0.0f);
            lo.z = fmaxf(qlo + qj2 - 2.0f * g2.x, 0.0f);
            lo.w = fmaxf(qlo + qj3 - 2.0f * g3.x, 0.0f);
            hi.x = fmaxf(qhi + qj0 - 2.0f * g0.y, 0.0f);
            hi.y = fmaxf(qhi + qj1 - 2.0f * g1.y, 0.0f);
            hi.z = fmaxf(qhi + qj2 - 2.0f * g2.y, 0.0f);
            hi.w = fmaxf(qhi + qj3 - 2.0f * g3.y, 0.0f);
            *(float4*)&g_dist[k][b][r][tj]     = lo;
            *(float4*)&g_dist[k][b][r + 1][tj] = hi;
        }
    }
}

// ---------------------------------------------------------------------------
// Kernel 4: fuse bands, row-max, logits, gumbel argmax -> binary
// single-logf form: y0 >= y1  <=>  l0 + g0 >= -l0 + g1
// ---------------------------------------------------------------------------
__global__ __launch_bounds__(256) void mask_kernel(const float* __restrict__ fw,
                                                   const float* __restrict__ gum,
                                                   float* __restrict__ out) {
    const int t = threadIdx.x;
    const int g = t >> 6;
    const int j = t & 63;
    const int bi = blockIdx.x * 4 + g;
    const int b = bi >> 6;
    const int i = bi & 63;

    const float f0 = fw[0], f1 = fw[1], f2 = fw[2];
    const float m = fmaxf(f0, fmaxf(f1, f2));
    const float e0 = expf(f0 - m), e1 = expf(f1 - m), e2 = expf(f2 - m);
    const float inv = 1.0f / (e0 + e1 + e2);
    const float w0 = e0 * inv, w1 = e1 * inv, w2 = e2 * inv;

    const float dsum = g_dist[0][b][i][j] * w0
                     + g_dist[1][b][i][j] * w1
                     + g_dist[2][b][i][j] * w2;

    const float e = 1.0f / (dsum + 1e-10f);
    const float emask = (j == i) ? 0.0f : e;

    __shared__ float red[8];
    float v = emask;
    #pragma unroll
    for (int o = 16; o; o >>= 1) v = fmaxf(v, __shfl_xor_sync(0xffffffffu, v, o));
    if ((t & 31) == 0) red[t >> 5] = v;
    __syncthreads();
    const float emax = fmaxf(red[2 * g], red[2 * g + 1]);

    float p = emask / emax;
    p = (j == i) ? 0.99f : p * 0.99f;

    const float l0 = logf(p / (1.0f - p));   // l1 = -l0 exactly in R

    const size_t gidx = ((size_t)(b * 4096 + i * 64 + j)) * 2;
    const float y0 = l0 + gum[gidx + 0];
    const float y1 = -l0 + gum[gidx + 1];

    out[b * 4096 + i * 64 + j] = (y0 >= y1) ? 1.0f : 0.0f;
}

// ---------------------------------------------------------------------------
extern "C" void kernel_launch(void* const* d_in, const int* in_sizes, int n_in,
                              void* d_out, int out_size) {
    const float* X   = (const float*)d_in[0];
    const float* A0  = (const float*)d_in[1];
    const float* A1  = (const float*)d_in[2];
    const float* A2  = (const float*)d_in[3];
    const float* fw  = (const float*)d_in[4];
    const float* gum = (const float*)d_in[5];
    float* out = (float*)d_out;

    twinit_kernel<<<1, 256>>>();
    fft_kernel<<<NROWS, 256>>>(X);
    gemm_kernel<<<dim3(6, 16, 3), 256>>>(A0, A1, A2);

    const int smem3 = SKP * TSP * sizeof(float)
                    + 256 * 8 * sizeof(unsigned long long);
    cudaFuncSetAttribute(gram_dist_kernel,
                         cudaFuncAttributeMaxDynamicSharedMemorySize, smem3);
    gram_dist_kernel<<<dim3(NB, 3), 512, smem3>>>();

    mask_kernel<<<512, 256>>>(fw, gum, out);
}

// round 13
// speedup vs baseline: 1.5769x; 1.0165x over previous
#include <cuda_runtime.h>
#include <math.h>
#include <stdint.h>

#define NB 32
#define NC 64
#define NL 2048
#define S0 341
#define S1 341
#define S2 343
#define SKP 352      // padded K stride
#define TSP 68       // gram transposed-smem row stride (64 + 4)
#define NROWS 2048   // NB * NC

// Scratch (device globals; allocation-free per harness rules)
__device__ float g_bands[3][NROWS][SKP];
__device__ float g_Y[3][NROWS][SKP];
__device__ float g_dist[3][NB][NC][NC];

// ---------------------------------------------------------------------------
// f32x2 helpers (Blackwell packed fp32: FFMA2)
// ---------------------------------------------------------------------------
__device__ __forceinline__ unsigned long long pk2(float lo, float hi) {
    unsigned long long r;
    asm("mov.b64 %0, {%1, %2};" : "=l"(r) : "f"(lo), "f"(hi));
    return r;
}
__device__ __forceinline__ void fma2(unsigned long long& d,
                                     unsigned long long a, unsigned long long b) {
    asm("fma.rn.f32x2 %0, %1, %2, %0;" : "+l"(d) : "l"(a), "l"(b));
}
__device__ __forceinline__ void add2(unsigned long long& d, unsigned long long a) {
    asm("add.rn.f32x2 %0, %0, %1;" : "+l"(d) : "l"(a));
}
__device__ __forceinline__ float2 upk2(unsigned long long v) {
    float lo, hi;
    asm("mov.b64 {%0, %1}, %2;" : "=f"(lo), "=f"(hi) : "l"(v));
    return make_float2(lo, hi);
}

// ---------------------------------------------------------------------------
// Kernel 1: rfft magnitude via real-packed 1024-pt radix-4 FFT (R8 version)
// ---------------------------------------------------------------------------
__device__ __forceinline__ unsigned drev10(unsigned n) {
    unsigned r = __brev(n) >> 22;
    return ((r & 0x155u) << 1) | ((r >> 1) & 0x155u);
}

__global__ __launch_bounds__(256) void fft_kernel(const float* __restrict__ X) {
    __shared__ float sre[1024], sim[1024], wre[1025], wim[1025];
    const int row = blockIdx.x;
    const int t = threadIdx.x;
    const float2* x2 = (const float2*)(X + (size_t)row * NL);

    #pragma unroll
    for (int m = 0; m < 4; m++) {
        const int i = t + m * 256;
        float sn, cs;
        sincospif((float)i * (1.0f / 512.0f), &sn, &cs);  // e^{-2*pi*i*i/1024}
        wre[i] = cs;
        wim[i] = -sn;
        const float2 v = x2[i];       // z[i] = x[2i] + i*x[2i+1]
        const unsigned dr = drev10((unsigned)i);
        sre[dr] = v.x;
        sim[dr] = v.y;
    }
    if (t == 0) { wre[1024] = -1.0f; wim[1024] = 0.0f; }
    __syncthreads();

    // stage 1 (m=1): contiguous quads, twiddle = 1, float4 access
    {
        float4 xr = *(float4*)&sre[4 * t];
        float4 xi = *(float4*)&sim[4 * t];
        const float s02r = xr.x + xr.z, s02i = xi.x + xi.z;
        const float d02r = xr.x - xr.z, d02i = xi.x - xi.z;
        const float s13r = xr.y + xr.w, s13i = xi.y + xi.w;
        const float d13r = xr.y - xr.w, d13i = xi.y - xi.w;
        float4 yr, yi;
        yr.x = s02r + s13r;  yi.x = s02i + s13i;
        yr.y = d02r + d13i;  yi.y = d02i - d13r;
        yr.z = s02r - s13r;  yi.z = s02i - s13i;
        yr.w = d02r - d13i;  yi.w = d02i + d13r;
        *(float4*)&sre[4 * t] = yr;
        *(float4*)&sim[4 * t] = yi;
    }
    __syncthreads();

    // stages 2..5
    #pragma unroll
    for (int s = 2; s <= 5; s++) {
        const int mm = 1 << (2 * (s - 1));
        const int j = t & (mm - 1);
        const int base = ((t >> (2 * (s - 1))) << (2 * s)) + j;
        const int r1 = j << (10 - 2 * s);

        const float x0r = sre[base],          x0i = sim[base];
        const float x1r = sre[base + mm],     x1i = sim[base + mm];
        const float x2r = sre[base + 2 * mm], x2i = sim[base + 2 * mm];
        const float x3r = sre[base + 3 * mm], x3i = sim[base + 3 * mm];
        const float w1r = wre[r1],     w1i = wim[r1];
        const float w2r = wre[2 * r1], w2i = wim[2 * r1];
        const float w3r = wre[3 * r1], w3i = wim[3 * r1];

        const float u1r = x1r * w1r - x1i * w1i, u1i = x1r * w1i + x1i * w1r;
        const float u2r = x2r * w2r - x2i * w2i, u2i = x2r * w2i + x2i * w2r;
        const float u3r = x3r * w3r - x3i * w3i, u3i = x3r * w3i + x3i * w3r;

        const float s02r = x0r + u2r, s02i = x0i + u2i;
        const float d02r = x0r - u2r, d02i = x0i - u2i;
        const float s13r = u1r + u3r, s13i = u1i + u3i;
        const float d13r = u1r - u3r, d13i = u1i - u3i;

        sre[base]          = s02r + s13r;  sim[base]          = s02i + s13i;
        sre[base + mm]     = d02r + d13i;  sim[base + mm]     = d02i - d13r;
        sre[base + 2 * mm] = s02r - s13r;  sim[base + 2 * mm] = s02i - s13i;
        sre[base + 3 * mm] = d02r - d13i;  sim[base + 3 * mm] = d02i + d13r;
        __syncthreads();
    }

    // untangle real-packed spectrum + magnitude -> zero-padded band slabs
    const float CR = 0.999995293809576f;    // cos(pi/1024)
    const float CI = -0.003067956762966f;   // -sin(pi/1024)
    for (int pos = t; pos < 3 * SKP; pos += 256) {
        int band, off, k, sk;
        if (pos < SKP)            { band = 0; off = pos;           k = off;       sk = S0; }
        else if (pos < 2 * SKP)   { band = 1; off = pos - SKP;     k = S0 + off;  sk = S1; }
        else                      { band = 2; off = pos - 2 * SKP; k = 682 + off; sk = S2; }
        float mag = 0.0f;
        if (off < sk) {
            const int ka = k & 1023;
            const int kb = (1024 - k) & 1023;
            const float z1r = sre[ka], z1i = sim[ka];
            const float z2r = sre[kb], z2i = sim[kb];
            const float zer = z1r + z2r, zei = z1i - z2i;        // 2*Ze
            const float zor = z1i + z2i, zoi = z2r - z1r;        // 2*Zo
            const int m = k >> 1;
            float cs = wre[m], msn = wim[m];                     // e^{-i*pi*m/512}
            if (k & 1) {
                const float c2 = cs * CR - msn * CI;
                msn = cs * CI + msn * CR;
                cs = c2;
            }
            const float xr = zer + cs * zor - msn * zoi;
            const float xi = zei + cs * zoi + msn * zor;
            mag = 0.5f * sqrtf(xr * xr + xi * xi);
        }
        (&g_bands[0][0][0])[((size_t)band * NROWS + row) * SKP + off] = mag;
    }
}

// ---------------------------------------------------------------------------
// Kernel 2: Y[k][r][d] = sum_s band[k][r][s] * A_k[d][s]   (R8 version)
// 128(r) x 64(d) tiles, 256 threads, 8x4 row-paired f32x2. grid (6, 16, 3)
// ---------------------------------------------------------------------------
__global__ __launch_bounds__(256) void gemm_kernel(const float* __restrict__ A0,
                                                   const float* __restrict__ A1,
                                                   const float* __restrict__ A2) {
    __shared__ float Xs[2][16][128];
    __shared__ float As[2][16][64];

    const int k = blockIdx.z;
    const int sk = (k == 2) ? S2 : S0;
    const float* A = (k == 0) ? A0 : ((k == 1) ? A1 : A2);
    const int d0 = blockIdx.x * 64;
    const int r0 = blockIdx.y * 128;
    const int t = threadIdx.x;
    const int tx = t & 15;      // d group: 4 cols
    const int ty = t >> 4;      // r group: 8 rows (4 pairs)
    const float* band = &g_bands[k][0][0];

    const int xlr = t & 127;
    const int xlh = (t >> 7) * 8;
    const int alr = t & 63;
    const int alh = (t >> 6) * 4;

    const int ad = d0 + alr;
    const bool dok = ad < sk;
    const float* arow = A + (size_t)ad * sk;

    unsigned long long acc[4][4];
    #pragma unroll
    for (int p = 0; p < 4; p++)
        #pragma unroll
        for (int j = 0; j < 4; j++) acc[p][j] = 0ull;

    float4 bx0, bx1, ba0;

#define LDG_TILE(kt)                                                            \
    do {                                                                        \
        const float* xp = &band[(size_t)(r0 + xlr) * SKP + (kt) + xlh];         \
        bx0 = *(const float4*)xp;  bx1 = *(const float4*)(xp + 4);              \
        const int s_ = (kt) + alh;                                              \
        ba0.x = (dok && s_ + 0 < sk) ? arow[s_ + 0] : 0.0f;                     \
        ba0.y = (dok && s_ + 1 < sk) ? arow[s_ + 1] : 0.0f;                     \
        ba0.z = (dok && s_ + 2 < sk) ? arow[s_ + 2] : 0.0f;                     \
        ba0.w = (dok && s_ + 3 < sk) ? arow[s_ + 3] : 0.0f;                     \
    } while (0)

#define STS_TILE(buf)                                                           \
    do {                                                                        \
        Xs[buf][xlh + 0][xlr] = bx0.x;  Xs[buf][xlh + 1][xlr] = bx0.y;          \
        Xs[buf][xlh + 2][xlr] = bx0.z;  Xs[buf][xlh + 3][xlr] = bx0.w;          \
        Xs[buf][xlh + 4][xlr] = bx1.x;  Xs[buf][xlh + 5][xlr] = bx1.y;          \
        Xs[buf][xlh + 6][xlr] = bx1.z;  Xs[buf][xlh + 7][xlr] = bx1.w;          \
        As[buf][alh + 0][alr] = ba0.x;  As[buf][alh + 1][alr] = ba0.y;          \
        As[buf][alh + 2][alr] = ba0.z;  As[buf][alh + 3][alr] = ba0.w;          \
    } while (0)

    LDG_TILE(0);
    STS_TILE(0);
    __syncthreads();

    const int NT = SKP / 16;  // 22
    for (int kt = 0; kt < NT; kt++) {
        const int buf = kt & 1;
        if (kt + 1 < NT) LDG_TILE((kt + 1) * 16);

        #pragma unroll
        for (int kk = 0; kk < 16; kk++) {
            const ulonglong2 a01 = *(const ulonglong2*)&Xs[buf][kk][ty * 8];
            const ulonglong2 a23 = *(const ulonglong2*)&Xs[buf][kk][ty * 8 + 4];
            const float4 b = *(const float4*)&As[buf][kk][tx * 4];
            const unsigned long long bd0 = pk2(b.x, b.x);
            const unsigned long long bd1 = pk2(b.y, b.y);
            const unsigned long long bd2 = pk2(b.z, b.z);
            const unsigned long long bd3 = pk2(b.w, b.w);
            fma2(acc[0][0], a01.x, bd0);  fma2(acc[0][1], a01.x, bd1);
            fma2(acc[0][2], a01.x, bd2);  fma2(acc[0][3], a01.x, bd3);
            fma2(acc[1][0], a01.y, bd0);  fma2(acc[1][1], a01.y, bd1);
            fma2(acc[1][2], a01.y, bd2);  fma2(acc[1][3], a01.y, bd3);
            fma2(acc[2][0], a23.x, bd0);  fma2(acc[2][1], a23.x, bd1);
            fma2(acc[2][2], a23.x, bd2);  fma2(acc[2][3], a23.x, bd3);
            fma2(acc[3][0], a23.y, bd0);  fma2(acc[3][1], a23.y, bd1);
            fma2(acc[3][2], a23.y, bd2);  fma2(acc[3][3], a23.y, bd3);
        }
        if (kt + 1 < NT) STS_TILE(buf ^ 1);
        __syncthreads();
    }

    const int d = d0 + tx * 4;
    if (d < SKP) {            // block d0=320 covers d up to 383
        #pragma unroll
        for (int p = 0; p < 4; p++) {
            const float2 v0 = upk2(acc[p][0]);
            const float2 v1 = upk2(acc[p][1]);
            const float2 v2 = upk2(acc[p][2]);
            const float2 v3 = upk2(acc[p][3]);
            const int r = r0 + ty * 8 + 2 * p;
            float4 lo = make_float4(v0.x, v1.x, v2.x, v3.x);
            float4 hi = make_float4(v0.y, v1.y, v2.y, v3.y);
            *(float4*)&g_Y[k][r][d]     = lo;
            *(float4*)&g_Y[k][r + 1][d] = hi;
        }
    }
#undef LDG_TILE
#undef STS_TILE
}

// ---------------------------------------------------------------------------
// Kernel 3: gram/dist (R8 version — 1024 threads, 4-way K-split)
// ---------------------------------------------------------------------------
__global__ __launch_bounds__(1024) void gram_dist_kernel() {
    extern __shared__ float smemf[];
    float* sYT = smemf;                                                  // 352*TSP
    unsigned long long* part = (unsigned long long*)(smemf + SKP * TSP); // [3][256][8]
    __shared__ float q[64];

    const int b = blockIdx.x;
    const int k = blockIdx.y;
    const int t = threadIdx.x;

    {
        const int r_ = t & 7;
        const int c4 = t >> 3;       // 0..127
        if (c4 < SKP / 4) {
            const float* src = &g_Y[k][b * 64][0];
            #pragma unroll
            for (int rb = 0; rb < 64; rb += 8) {
                const int r = rb + r_;
                const float4 v = *(const float4*)&src[(size_t)r * SKP + c4 * 4];
                const int d = c4 * 4;
                sYT[(d + 0) * TSP + r] = v.x;
                sYT[(d + 1) * TSP + r] = v.y;
                sYT[(d + 2) * TSP + r] = v.z;
                sYT[(d + 3) * TSP + r] = v.w;
            }
        }
    }
    __syncthreads();

    const int half = t >> 8;       // K-split group 0..3
    const int tt = t & 255;
    const int ty = tt >> 4;
    const int tx = tt & 15;
    const int ti = ty * 4;
    const int tj = tx * 4;

    unsigned long long acc[2][4];
    #pragma unroll
    for (int p = 0; p < 2; p++)
        #pragma unroll
        for (int j = 0; j < 4; j++) acc[p][j] = 0ull;

    const float* base = &sYT[half * 88 * TSP];
    #pragma unroll 4
    for (int dd = 0; dd < 88; dd++) {
        const float* rowp = base + dd * TSP;
        const ulonglong2 a = *(const ulonglong2*)&rowp[ti];
        const float4 bb = *(const float4*)&rowp[tj];
        const unsigned long long bd0 = pk2(bb.x, bb.x);
        const unsigned long long bd1 = pk2(bb.y, bb.y);
        const unsigned long long bd2 = pk2(bb.z, bb.z);
        const unsigned long long bd3 = pk2(bb.w, bb.w);
        fma2(acc[0][0], a.x, bd0);  fma2(acc[0][1], a.x, bd1);
        fma2(acc[0][2], a.x, bd2);  fma2(acc[0][3], a.x, bd3);
        fma2(acc[1][0], a.y, bd0);  fma2(acc[1][1], a.y, bd1);
        fma2(acc[1][2], a.y, bd2);  fma2(acc[1][3], a.y, bd3);
    }

    if (half != 0) {
        unsigned long long* dst = &part[((half - 1) * 256 + tt) * 8];
        #pragma unroll
        for (int p = 0; p < 2; p++)
            #pragma unroll
            for (int j = 0; j < 4; j++) dst[p * 4 + j] = acc[p][j];
    }
    __syncthreads();

    if (half == 0) {
        #pragma unroll
        for (int h = 0; h < 3; h++) {
            const unsigned long long* src = &part[(h * 256 + tt) * 8];
            #pragma unroll
            for (int p = 0; p < 2; p++)
                #pragma unroll
                for (int j = 0; j < 4; j++) add2(acc[p][j], src[p * 4 + j]);
        }
        if (ty == tx) {
            q[ti + 0] = upk2(acc[0][0]).x;
            q[ti + 1] = upk2(acc[0][1]).y;
            q[ti + 2] = upk2(acc[1][2]).x;
            q[ti + 3] = upk2(acc[1][3]).y;
        }
    }
    __syncthreads();

    if (half == 0) {
        #pragma unroll
        for (int p = 0; p < 2; p++) {
            const float2 g0 = upk2(acc[p][0]);
            const float2 g1 = upk2(acc[p][1]);
            const float2 g2 = upk2(acc[p][2]);
            const float2 g3 = upk2(acc[p][3]);
            const float qj0 = q[tj + 0], qj1 = q[tj + 1];
            const float qj2 = q[tj + 2], qj3 = q[tj + 3];
            const int r = ti + 2 * p;
            const float qlo = q[r], qhi = q[r + 1];
            float4 lo, hi;
            lo.x = fmaxf(qlo + qj0 - 2.0f * g0.x, 0.0f);
            lo.y = fmaxf(qlo + qj1 - 2.0f * g1.x, 0.0f);
            lo.z = fmaxf(qlo + qj2 - 2.0f * g2.x, 0.0f);
            lo.w = fmaxf(qlo + qj3 - 2.0f * g3.x, 0.0f);
            hi.x = fmaxf(qhi + qj0 - 2.0f * g0.y, 0.0f);
            hi.y = fmaxf(qhi + qj1 - 2.0f * g1.y, 0.0f);
            hi.z = fmaxf(qhi + qj2 - 2.0f * g2.y, 0.0f);
            hi.w = fmaxf(qhi + qj3 - 2.0f * g3.y, 0.0f);
            *(float4*)&g_dist[k][b][r][tj]     = lo;
            *(float4*)&g_dist[k][b][r + 1][tj] = hi;
        }
    }
}

// ---------------------------------------------------------------------------
// Kernel 4: fuse bands, row-max, logits, gumbel argmax -> binary
// single-logf form: y0 >= y1  <=>  l0 + g0 >= -l0 + g1
// ---------------------------------------------------------------------------
__global__ __launch_bounds__(256) void mask_kernel(const float* __restrict__ fw,
                                                   const float* __restrict__ gum,
                                                   float* __restrict__ out) {
    const int t = threadIdx.x;
    const int g = t >> 6;
    const int j = t & 63;
    const int bi = blockIdx.x * 4 + g;
    const int b = bi >> 6;
    const int i = bi & 63;

    const float f0 = fw[0], f1 = fw[1], f2 = fw[2];
    const float m = fmaxf(f0, fmaxf(f1, f2));
    const float e0 = expf(f0 - m), e1 = expf(f1 - m), e2 = expf(f2 - m);
    const float inv = 1.0f / (e0 + e1 + e2);
    const float w0 = e0 * inv, w1 = e1 * inv, w2 = e2 * inv;

    const float dsum = g_dist[0][b][i][j] * w0
                     + g_dist[1][b][i][j] * w1
                     + g_dist[2][b][i][j] * w2;

    const float e = 1.0f / (dsum + 1e-10f);
    const float emask = (j == i) ? 0.0f : e;

    __shared__ float red[8];
    float v = emask;
    #pragma unroll
    for (int o = 16; o; o >>= 1) v = fmaxf(v, __shfl_xor_sync(0xffffffffu, v, o));
    if ((t & 31) == 0) red[t >> 5] = v;
    __syncthreads();
    const float emax = fmaxf(red[2 * g], red[2 * g + 1]);

    float p = emask / emax;
    p = (j == i) ? 0.99f : p * 0.99f;

    const float l0 = logf(p / (1.0f - p));   // l1 = -l0 exactly in R

    const size_t gidx = ((size_t)(b * 4096 + i * 64 + j)) * 2;
    const float y0 = l0 + gum[gidx + 0];
    const float y1 = -l0 + gum[gidx + 1];

    out[b * 4096 + i * 64 + j] = (y0 >= y1) ? 1.0f : 0.0f;
}

// ---------------------------------------------------------------------------
extern "C" void kernel_launch(void* const* d_in, const int* in_sizes, int n_in,
                              void* d_out, int out_size) {
    const float* X   = (const float*)d_in[0];
    const float* A0  = (const float*)d_in[1];
    const float* A1  = (const float*)d_in[2];
    const float* A2  = (const float*)d_in[3];
    const float* fw  = (const float*)d_in[4];
    const float* gum = (const float*)d_in[5];
    float* out = (float*)d_out;

    fft_kernel<<<NROWS, 256>>>(X);
    gemm_kernel<<<dim3(6, 16, 3), 256>>>(A0, A1, A2);

    const int smem3 = SKP * TSP * sizeof(float)
                    + 3 * 256 * 8 * sizeof(unsigned long long);
    cudaFuncSetAttribute(gram_dist_kernel,
                         cudaFuncAttributeMaxDynamicSharedMemorySize, smem3);
    gram_dist_kernel<<<dim3(NB, 3), 1024, smem3>>>();

    mask_kernel<<<512, 256>>>(fw, gum, out);
}

// round 14
// speedup vs baseline: 1.6815x; 1.0663x over previous
#include <cuda_runtime.h>
#include <math.h>
#include <stdint.h>

#define NB 32
#define NC 64
#define NL 2048
#define S0 341
#define S1 341
#define S2 343
#define SKP 352      // padded K stride
#define TSP 68       // gram transposed-smem row stride (64 + 4)
#define NROWS 2048   // NB * NC

// bank-conflict-avoiding index padding for the FFT smem arrays
#define SIDX(a) ((a) + ((a) >> 5))
#define FFTPAD 1056  // 1024 + 32

// Scratch (device globals; allocation-free per harness rules)
__device__ float g_bands[3][NROWS][SKP];
__device__ float g_Y[3][NROWS][SKP];
__device__ float g_dist[3][NB][NC][NC];

// ---------------------------------------------------------------------------
// f32x2 helpers (Blackwell packed fp32: FFMA2)
// ---------------------------------------------------------------------------
__device__ __forceinline__ unsigned long long pk2(float lo, float hi) {
    unsigned long long r;
    asm("mov.b64 %0, {%1, %2};" : "=l"(r) : "f"(lo), "f"(hi));
    return r;
}
__device__ __forceinline__ void fma2(unsigned long long& d,
                                     unsigned long long a, unsigned long long b) {
    asm("fma.rn.f32x2 %0, %1, %2, %0;" : "+l"(d) : "l"(a), "l"(b));
}
__device__ __forceinline__ void add2(unsigned long long& d, unsigned long long a) {
    asm("add.rn.f32x2 %0, %0, %1;" : "+l"(d) : "l"(a));
}
__device__ __forceinline__ float2 upk2(unsigned long long v) {
    float lo, hi;
    asm("mov.b64 {%0, %1}, %2;" : "=f"(lo), "=f"(hi) : "l"(v));
    return make_float2(lo, hi);
}

// ---------------------------------------------------------------------------
// Kernel 1: rfft magnitude via real-packed 1024-pt radix-4 FFT
// - padded smem indexing (SIDX): scatter store conflict-free, stages <=2-way
// - single sincospif per thread; other 3 twiddle quadrants via rotations
// ---------------------------------------------------------------------------
__device__ __forceinline__ unsigned drev10(unsigned n) {
    unsigned r = __brev(n) >> 22;                       // 10-bit bit reversal
    return ((r & 0x155u) << 1) | ((r >> 1) & 0x155u);   // -> base-4 digit reversal
}

__global__ __launch_bounds__(256) void fft_kernel(const float* __restrict__ X) {
    __shared__ float sre[FFTPAD], sim[FFTPAD], wre[1025], wim[1025];
    const int row = blockIdx.x;
    const int t = threadIdx.x;
    const float2* x2 = (const float2*)(X + (size_t)row * NL);

    // twiddle fill: w(j) = e^{-i*pi*j/512}; quadrants by rotation
    {
        float sn, cs;
        sincospif((float)t * (1.0f / 512.0f), &sn, &cs);
        const float a = cs, b = -sn;
        wre[t]       = a;    wim[t]       = b;
        wre[t + 256] = b;    wim[t + 256] = -a;   // * (-i)
        wre[t + 512] = -a;   wim[t + 512] = -b;   // * (-1)
        wre[t + 768] = -b;   wim[t + 768] = a;    // * (+i)
    }
    if (t == 0) { wre[1024] = -1.0f; wim[1024] = 0.0f; }

    // load + bit-reversed scatter (conflict-free under SIDX)
    #pragma unroll
    for (int m = 0; m < 4; m++) {
        const int i = t + m * 256;
        const float2 v = x2[i];       // z[i] = x[2i] + i*x[2i+1]
        const unsigned dr = drev10((unsigned)i);
        sre[SIDX(dr)] = v.x;
        sim[SIDX(dr)] = v.y;
    }
    __syncthreads();

    // stage 1 (m=1): contiguous quads, twiddle = 1 (scalar, padded indices)
    {
        const int s1 = 4 * t + ((4 * t) >> 5);   // no 32-boundary crossing in quad
        const float x0r = sre[s1 + 0], x1r = sre[s1 + 1];
        const float x2r = sre[s1 + 2], x3r = sre[s1 + 3];
        const float x0i = sim[s1 + 0], x1i = sim[s1 + 1];
        const float x2i = sim[s1 + 2], x3i = sim[s1 + 3];
        const float s02r = x0r + x2r, s02i = x0i + x2i;
        const float d02r = x0r - x2r, d02i = x0i - x2i;
        const float s13r = x1r + x3r, s13i = x1i + x3i;
        const float d13r = x1r - x3r, d13i = x1i - x3i;
        sre[s1 + 0] = s02r + s13r;  sim[s1 + 0] = s02i + s13i;
        sre[s1 + 1] = d02r + d13i;  sim[s1 + 1] = d02i - d13r;
        sre[s1 + 2] = s02r - s13r;  sim[s1 + 2] = s02i - s13i;
        sre[s1 + 3] = d02r - d13i;  sim[s1 + 3] = d02i + d13r;
    }
    __syncthreads();

    // stages 2..5
    #pragma unroll
    for (int s = 2; s <= 5; s++) {
        const int mm = 1 << (2 * (s - 1));
        const int j = t & (mm - 1);
        const int base = ((t >> (2 * (s - 1))) << (2 * s)) + j;
        const int r1 = j << (10 - 2 * s);

        const int p0 = SIDX(base);
        const int p1 = SIDX(base + mm);
        const int p2 = SIDX(base + 2 * mm);
        const int p3 = SIDX(base + 3 * mm);

        const float x0r = sre[p0], x0i = sim[p0];
        const float x1r = sre[p1], x1i = sim[p1];
        const float x2r = sre[p2], x2i = sim[p2];
        const float x3r = sre[p3], x3i = sim[p3];
        const float w1r = wre[r1],     w1i = wim[r1];
        const float w2r = wre[2 * r1], w2i = wim[2 * r1];
        const float w3r = wre[3 * r1], w3i = wim[3 * r1];

        const float u1r = x1r * w1r - x1i * w1i, u1i = x1r * w1i + x1i * w1r;
        const float u2r = x2r * w2r - x2i * w2i, u2i = x2r * w2i + x2i * w2r;
        const float u3r = x3r * w3r - x3i * w3i, u3i = x3r * w3i + x3i * w3r;

        const float s02r = x0r + u2r, s02i = x0i + u2i;
        const float d02r = x0r - u2r, d02i = x0i - u2i;
        const float s13r = u1r + u3r, s13i = u1i + u3i;
        const float d13r = u1r - u3r, d13i = u1i - u3i;

        sre[p0] = s02r + s13r;  sim[p0] = s02i + s13i;
        sre[p1] = d02r + d13i;  sim[p1] = d02i - d13r;
        sre[p2] = s02r - s13r;  sim[p2] = s02i - s13i;
        sre[p3] = d02r - d13i;  sim[p3] = d02i + d13r;
        __syncthreads();
    }

    // untangle real-packed spectrum + magnitude -> zero-padded band slabs
    const float CR = 0.999995293809576f;    // cos(pi/1024)
    const float CI = -0.003067956762966f;   // -sin(pi/1024)
    for (int pos = t; pos < 3 * SKP; pos += 256) {
        int band, off, k, sk;
        if (pos < SKP)            { band = 0; off = pos;           k = off;       sk = S0; }
        else if (pos < 2 * SKP)   { band = 1; off = pos - SKP;     k = S0 + off;  sk = S1; }
        else                      { band = 2; off = pos - 2 * SKP; k = 682 + off; sk = S2; }
        float mag = 0.0f;
        if (off < sk) {
            const int ka = SIDX(k & 1023);
            const int kb = SIDX((1024 - k) & 1023);
            const float z1r = sre[ka], z1i = sim[ka];
            const float z2r = sre[kb], z2i = sim[kb];
            const float zer = z1r + z2r, zei = z1i - z2i;        // 2*Ze
            const float zor = z1i + z2i, zoi = z2r - z1r;        // 2*Zo
            const int m = k >> 1;
            float cs = wre[m], msn = wim[m];                     // e^{-i*pi*m/512}
            if (k & 1) {
                const float c2 = cs * CR - msn * CI;
                msn = cs * CI + msn * CR;
                cs = c2;
            }
            const float xr = zer + cs * zor - msn * zoi;
            const float xi = zei + cs * zoi + msn * zor;
            mag = 0.5f * sqrtf(xr * xr + xi * xi);
        }
        (&g_bands[0][0][0])[((size_t)band * NROWS + row) * SKP + off] = mag;
    }
}

// ---------------------------------------------------------------------------
// Kernel 2: Y[k][r][d] = sum_s band[k][r][s] * A_k[d][s]   (R8 version)
// 128(r) x 64(d) tiles, 256 threads, 8x4 row-paired f32x2. grid (6, 16, 3)
// ---------------------------------------------------------------------------
__global__ __launch_bounds__(256) void gemm_kernel(const float* __restrict__ A0,
                                                   const float* __restrict__ A1,
                                                   const float* __restrict__ A2) {
    __shared__ float Xs[2][16][128];
    __shared__ float As[2][16][64];

    const int k = blockIdx.z;
    const int sk = (k == 2) ? S2 : S0;
    const float* A = (k == 0) ? A0 : ((k == 1) ? A1 : A2);
    const int d0 = blockIdx.x * 64;
    const int r0 = blockIdx.y * 128;
    const int t = threadIdx.x;
    const int tx = t & 15;      // d group: 4 cols
    const int ty = t >> 4;      // r group: 8 rows (4 pairs)
    const float* band = &g_bands[k][0][0];

    const int xlr = t & 127;
    const int xlh = (t >> 7) * 8;
    const int alr = t & 63;
    const int alh = (t >> 6) * 4;

    const int ad = d0 + alr;
    const bool dok = ad < sk;
    const float* arow = A + (size_t)ad * sk;

    unsigned long long acc[4][4];
    #pragma unroll
    for (int p = 0; p < 4; p++)
        #pragma unroll
        for (int j = 0; j < 4; j++) acc[p][j] = 0ull;

    float4 bx0, bx1, ba0;

#define LDG_TILE(kt)                                                            \
    do {                                                                        \
        const float* xp = &band[(size_t)(r0 + xlr) * SKP + (kt) + xlh];         \
        bx0 = *(const float4*)xp;  bx1 = *(const float4*)(xp + 4);              \
        const int s_ = (kt) + alh;                                              \
        ba0.x = (dok && s_ + 0 < sk) ? arow[s_ + 0] : 0.0f;                     \
        ba0.y = (dok && s_ + 1 < sk) ? arow[s_ + 1] : 0.0f;                     \
        ba0.z = (dok && s_ + 2 < sk) ? arow[s_ + 2] : 0.0f;                     \
        ba0.w = (dok && s_ + 3 < sk) ? arow[s_ + 3] : 0.0f;                     \
    } while (0)

#define STS_TILE(buf)                                                           \
    do {                                                                        \
        Xs[buf][xlh + 0][xlr] = bx0.x;  Xs[buf][xlh + 1][xlr] = bx0.y;          \
        Xs[buf][xlh + 2][xlr] = bx0.z;  Xs[buf][xlh + 3][xlr] = bx0.w;          \
        Xs[buf][xlh + 4][xlr] = bx1.x;  Xs[buf][xlh + 5][xlr] = bx1.y;          \
        Xs[buf][xlh + 6][xlr] = bx1.z;  Xs[buf][xlh + 7][xlr] = bx1.w;          \
        As[buf][alh + 0][alr] = ba0.x;  As[buf][alh + 1][alr] = ba0.y;          \
        As[buf][alh + 2][alr] = ba0.z;  As[buf][alh + 3][alr] = ba0.w;          \
    } while (0)

    LDG_TILE(0);
    STS_TILE(0);
    __syncthreads();

    const int NT = SKP / 16;  // 22
    for (int kt = 0; kt < NT; kt++) {
        const int buf = kt & 1;
        if (kt + 1 < NT) LDG_TILE((kt + 1) * 16);

        #pragma unroll
        for (int kk = 0; kk < 16; kk++) {
            const ulonglong2 a01 = *(const ulonglong2*)&Xs[buf][kk][ty * 8];
            const ulonglong2 a23 = *(const ulonglong2*)&Xs[buf][kk][ty * 8 + 4];
            const float4 b = *(const float4*)&As[buf][kk][tx * 4];
            const unsigned long long bd0 = pk2(b.x, b.x);
            const unsigned long long bd1 = pk2(b.y, b.y);
            const unsigned long long bd2 = pk2(b.z, b.z);
            const unsigned long long bd3 = pk2(b.w, b.w);
            fma2(acc[0][0], a01.x, bd0);  fma2(acc[0][1], a01.x, bd1);
            fma2(acc[0][2], a01.x, bd2);  fma2(acc[0][3], a01.x, bd3);
            fma2(acc[1][0], a01.y, bd0);  fma2(acc[1][1], a01.y, bd1);
            fma2(acc[1][2], a01.y, bd2);  fma2(acc[1][3], a01.y, bd3);
            fma2(acc[2][0], a23.x, bd0);  fma2(acc[2][1], a23.x, bd1);
            fma2(acc[2][2], a23.x, bd2);  fma2(acc[2][3], a23.x, bd3);
            fma2(acc[3][0], a23.y, bd0);  fma2(acc[3][1], a23.y, bd1);
            fma2(acc[3][2], a23.y, bd2);  fma2(acc[3][3], a23.y, bd3);
        }
        if (kt + 1 < NT) STS_TILE(buf ^ 1);
        __syncthreads();
    }

    const int d = d0 + tx * 4;
    if (d < SKP) {            // block d0=320 covers d up to 383
        #pragma unroll
        for (int p = 0; p < 4; p++) {
            const float2 v0 = upk2(acc[p][0]);
            const float2 v1 = upk2(acc[p][1]);
            const float2 v2 = upk2(acc[p][2]);
            const float2 v3 = upk2(acc[p][3]);
            const int r = r0 + ty * 8 + 2 * p;
            float4 lo = make_float4(v0.x, v1.x, v2.x, v3.x);
            float4 hi = make_float4(v0.y, v1.y, v2.y, v3.y);
            *(float4*)&g_Y[k][r][d]     = lo;
            *(float4*)&g_Y[k][r + 1][d] = hi;
        }
    }
#undef LDG_TILE
#undef STS_TILE
}

// ---------------------------------------------------------------------------
// Kernel 3: gram/dist (R8 version — 1024 threads, 4-way K-split)
// ---------------------------------------------------------------------------
__global__ __launch_bounds__(1024) void gram_dist_kernel() {
    extern __shared__ float smemf[];
    float* sYT = smemf;                                                  // 352*TSP
    unsigned long long* part = (unsigned long long*)(smemf + SKP * TSP); // [3][256][8]
    __shared__ float q[64];

    const int b = blockIdx.x;
    const int k = blockIdx.y;
    const int t = threadIdx.x;

    {
        const int r_ = t & 7;
        const int c4 = t >> 3;       // 0..127
        if (c4 < SKP / 4) {
            const float* src = &g_Y[k][b * 64][0];
            #pragma unroll
            for (int rb = 0; rb < 64; rb += 8) {
                const int r = rb + r_;
                const float4 v = *(const float4*)&src[(size_t)r * SKP + c4 * 4];
                const int d = c4 * 4;
                sYT[(d + 0) * TSP + r] = v.x;
                sYT[(d + 1) * TSP + r] = v.y;
                sYT[(d + 2) * TSP + r] = v.z;
                sYT[(d + 3) * TSP + r] = v.w;
            }
        }
    }
    __syncthreads();

    const int half = t >> 8;       // K-split group 0..3
    const int tt = t & 255;
    const int ty = tt >> 4;
    const int tx = tt & 15;
    const int ti = ty * 4;
    const int tj = tx * 4;

    unsigned long long acc[2][4];
    #pragma unroll
    for (int p = 0; p < 2; p++)
        #pragma unroll
        for (int j = 0; j < 4; j++) acc[p][j] = 0ull;

    const float* base = &sYT[half * 88 * TSP];
    #pragma unroll 4
    for (int dd = 0; dd < 88; dd++) {
        const float* rowp = base + dd * TSP;
        const ulonglong2 a = *(const ulonglong2*)&rowp[ti];
        const float4 bb = *(const float4*)&rowp[tj];
        const unsigned long long bd0 = pk2(bb.x, bb.x);
        const unsigned long long bd1 = pk2(bb.y, bb.y);
        const unsigned long long bd2 = pk2(bb.z, bb.z);
        const unsigned long long bd3 = pk2(bb.w, bb.w);
        fma2(acc[0][0], a.x, bd0);  fma2(acc[0][1], a.x, bd1);
        fma2(acc[0][2], a.x, bd2);  fma2(acc[0][3], a.x, bd3);
        fma2(acc[1][0], a.y, bd0);  fma2(acc[1][1], a.y, bd1);
        fma2(acc[1][2], a.y, bd2);  fma2(acc[1][3], a.y, bd3);
    }

    if (half != 0) {
        unsigned long long* dst = &part[((half - 1) * 256 + tt) * 8];
        #pragma unroll
        for (int p = 0; p < 2; p++)
            #pragma unroll
            for (int j = 0; j < 4; j++) dst[p * 4 + j] = acc[p][j];
    }
    __syncthreads();

    if (half == 0) {
        #pragma unroll
        for (int h = 0; h < 3; h++) {
            const unsigned long long* src = &part[(h * 256 + tt) * 8];
            #pragma unroll
            for (int p = 0; p < 2; p++)
                #pragma unroll
                for (int j = 0; j < 4; j++) add2(acc[p][j], src[p * 4 + j]);
        }
        if (ty == tx) {
            q[ti + 0] = upk2(acc[0][0]).x;
            q[ti + 1] = upk2(acc[0][1]).y;
            q[ti + 2] = upk2(acc[1][2]).x;
            q[ti + 3] = upk2(acc[1][3]).y;
        }
    }
    __syncthreads();

    if (half == 0) {
        #pragma unroll
        for (int p = 0; p < 2; p++) {
            const float2 g0 = upk2(acc[p][0]);
            const float2 g1 = upk2(acc[p][1]);
            const float2 g2 = upk2(acc[p][2]);
            const float2 g3 = upk2(acc[p][3]);
            const float qj0 = q[tj + 0], qj1 = q[tj + 1];
            const float qj2 = q[tj + 2], qj3 = q[tj + 3];
            const int r = ti + 2 * p;
            const float qlo = q[r], qhi = q[r + 1];
            float4 lo, hi;
            lo.x = fmaxf(qlo + qj0 - 2.0f * g0.x, 0.0f);
            lo.y = fmaxf(qlo + qj1 - 2.0f * g1.x, 0.0f);
            lo.z = fmaxf(qlo + qj2 - 2.0f * g2.x, 0.0f);
            lo.w = fmaxf(qlo + qj3 - 2.0f * g3.x, 0.0f);
            hi.x = fmaxf(qhi + qj0 - 2.0f * g0.y, 0.0f);
            hi.y = fmaxf(qhi + qj1 - 2.0f * g1.y, 0.0f);
            hi.z = fmaxf(qhi + qj2 - 2.0f * g2.y, 0.0f);
            hi.w = fmaxf(qhi + qj3 - 2.0f * g3.y, 0.0f);
            *(float4*)&g_dist[k][b][r][tj]     = lo;
            *(float4*)&g_dist[k][b][r + 1][tj] = hi;
        }
    }
}

// ---------------------------------------------------------------------------
// Kernel 4: fuse bands, row-max, logits, gumbel argmax -> binary
// single-logf form: y0 >= y1  <=>  l0 + g0 >= -l0 + g1
// ---------------------------------------------------------------------------
__global__ __launch_bounds__(256) void mask_kernel(const float* __restrict__ fw,
                                                   const float* __restrict__ gum,
                                                   float* __restrict__ out) {
    const int t = threadIdx.x;
    const int g = t >> 6;
    const int j = t & 63;
    const int bi = blockIdx.x * 4 + g;
    const int b = bi >> 6;
    const int i = bi & 63;

    const float f0 = fw[0], f1 = fw[1], f2 = fw[2];
    const float m = fmaxf(f0, fmaxf(f1, f2));
    const float e0 = expf(f0 - m), e1 = expf(f1 - m), e2 = expf(f2 - m);
    const float inv = 1.0f / (e0 + e1 + e2);
    const float w0 = e0 * inv, w1 = e1 * inv, w2 = e2 * inv;

    const float dsum = g_dist[0][b][i][j] * w0
                     + g_dist[1][b][i][j] * w1
                     + g_dist[2][b][i][j] * w2;

    const float e = 1.0f / (dsum + 1e-10f);
    const float emask = (j == i) ? 0.0f : e;

    __shared__ float red[8];
    float v = emask;
    #pragma unroll
    for (int o = 16; o; o >>= 1) v = fmaxf(v, __shfl_xor_sync(0xffffffffu, v, o));
    if ((t & 31) == 0) red[t >> 5] = v;
    __syncthreads();
    const float emax = fmaxf(red[2 * g], red[2 * g + 1]);

    float p = emask / emax;
    p = (j == i) ? 0.99f : p * 0.99f;

    const float l0 = logf(p / (1.0f - p));   // l1 = -l0 exactly in R

    const size_t gidx = ((size_t)(b * 4096 + i * 64 + j)) * 2;
    const float y0 = l0 + gum[gidx + 0];
    const float y1 = -l0 + gum[gidx + 1];

    out[b * 4096 + i * 64 + j] = (y0 >= y1) ? 1.0f : 0.0f;
}

// ---------------------------------------------------------------------------
extern "C" void kernel_launch(void* const* d_in, const int* in_sizes, int n_in,
                              void* d_out, int out_size) {
    const float* X   = (const float*)d_in[0];
    const float* A0  = (const float*)d_in[1];
    const float* A1  = (const float*)d_in[2];
    const float* A2  = (const float*)d_in[3];
    const float* fw  = (const float*)d_in[4];
    const float* gum = (const float*)d_in[5];
    float* out = (float*)d_out;

    fft_kernel<<<NROWS, 256>>>(X);
    gemm_kernel<<<dim3(6, 16, 3), 256>>>(A0, A1, A2);

    const int smem3 = SKP * TSP * sizeof(float)
                    + 3 * 256 * 8 * sizeof(unsigned long long);
    cudaFuncSetAttribute(gram_dist_kernel,
                         cudaFuncAttributeMaxDynamicSharedMemorySize, smem3);
    gram_dist_kernel<<<dim3(NB, 3), 1024, smem3>>>();

    mask_kernel<<<512, 256>>>(fw, gum, out);
}